// round 11
// baseline (speedup 1.0000x reference)
#include <cuda_runtime.h>
#include <cuda_bf16.h>
#include <cstdint>

#define BB 2
#define NN 2048
#define DD 512
#define HH 8
#define HD 64
#define ROWS (BB*NN)

// Scratch (no allocations allowed)
__device__ __nv_bfloat16 g_QKV[3][(size_t)ROWS * DD];   // Q,K,V projections
__device__ __nv_bfloat16 g_Xb[(size_t)ROWS * DD];       // x in bf16
__device__ __nv_bfloat16 g_Wb[3][(size_t)DD * DD];      // W_q/k/v in bf16
__device__ float g_c[ROWS];                             // gate vec (log2-scaled)
__device__ unsigned g_maxk_bits[BB * HH];               // max_j ||k_j||^2 (float bits)
__device__ unsigned g_maxc_bits[BB];                    // max_j c_j (monotone-encoded)

#define LOG2E 1.4426950408889634f
#define SCLOG (0.125f * LOG2E)

// ---------------------------------------------------------------------------
// helpers
// ---------------------------------------------------------------------------
__device__ __forceinline__ float ex2f(float x) {        // 2^x on MUFU
    float r;
    asm("ex2.approx.f32 %0, %1;" : "=f"(r) : "f"(x));
    return r;
}
__device__ __forceinline__ uint32_t pack_bf16(float lo, float hi) {
    uint32_t r;
    asm("cvt.rn.bf16x2.f32 %0, %1, %2;" : "=r"(r) : "f"(hi), "f"(lo));
    return r;
}
__device__ __forceinline__ unsigned enc_ord(float f) {  // monotone float->uint
    int i = __float_as_int(f);
    return (i < 0) ? ~(unsigned)i : ((unsigned)i | 0x80000000u);
}
__device__ __forceinline__ float dec_ord(unsigned u) {
    int i = (u & 0x80000000u) ? (int)(u & 0x7fffffffu) : (int)~u;
    return __int_as_float(i);
}
__device__ __forceinline__ void mma16(float* d, const uint32_t* a,
                                      uint32_t b0, uint32_t b1, const float* c) {
    asm("mma.sync.aligned.m16n8k16.row.col.f32.bf16.bf16.f32 "
        "{%0,%1,%2,%3}, {%4,%5,%6,%7}, {%8,%9}, {%10,%11,%12,%13};"
        : "=f"(d[0]), "=f"(d[1]), "=f"(d[2]), "=f"(d[3])
        : "r"(a[0]), "r"(a[1]), "r"(a[2]), "r"(a[3]),
          "r"(b0), "r"(b1),
          "f"(c[0]), "f"(c[1]), "f"(c[2]), "f"(c[3]));
}
__device__ __forceinline__ void ldm_x4(uint32_t* r, const void* ptr) {
    uint32_t a = (uint32_t)__cvta_generic_to_shared(ptr);
    asm volatile("ldmatrix.sync.aligned.m8n8.x4.shared.b16 "
                 "{%0,%1,%2,%3}, [%4];"
                 : "=r"(r[0]), "=r"(r[1]), "=r"(r[2]), "=r"(r[3]) : "r"(a));
}
__device__ __forceinline__ void ldm_x4_trans(uint32_t* r, const void* ptr) {
    uint32_t a = (uint32_t)__cvta_generic_to_shared(ptr);
    asm volatile("ldmatrix.sync.aligned.m8n8.x4.trans.shared.b16 "
                 "{%0,%1,%2,%3}, [%4];"
                 : "=r"(r[0]), "=r"(r[1]), "=r"(r[2]), "=r"(r[3]) : "r"(a));
}
__device__ __forceinline__ void cpa16(void* smem_dst, const void* gsrc) {
    uint32_t d = (uint32_t)__cvta_generic_to_shared(smem_dst);
    asm volatile("cp.async.cg.shared.global [%0], [%1], 16;" :: "r"(d), "l"(gsrc));
}
#define CP_COMMIT asm volatile("cp.async.commit_group;" ::: "memory")
#define CP_WAIT1  asm volatile("cp.async.wait_group 1;" ::: "memory")
#define CP_WAIT0  asm volatile("cp.async.wait_group 0;" ::: "memory")

// ---------------------------------------------------------------------------
// Kernel 0: one-shot fp32 -> bf16 conversion of x and W_q/k/v.
// Also resets the bound atomics (block 0) — runs first every graph replay.
// ---------------------------------------------------------------------------
__global__ __launch_bounds__(256)
void convert_kernel(const float* __restrict__ X, const float* __restrict__ Wq,
                    const float* __restrict__ Wk, const float* __restrict__ Wv)
{
    if (blockIdx.x == 0) {
        int t = threadIdx.x;
        if (t < BB * HH) g_maxk_bits[t] = 0u;             // ||k||^2 >= 0
        if (t < BB)      g_maxc_bits[t] = 0u;
    }
    int idx = blockIdx.x * 256 + threadIdx.x;
    const float* src;
    __nv_bfloat16* dst;
    size_t off;
    if (idx < 262144) {
        src = X; dst = g_Xb; off = (size_t)idx * 8;
    } else {
        int r = idx - 262144;
        int z = r >> 15;
        int o = r & 32767;
        src = (z == 0) ? Wq : (z == 1) ? Wk : Wv;
        dst = g_Wb[z]; off = (size_t)o * 8;
    }
    float4 v0 = *(const float4*)(src + off);
    float4 v1 = *(const float4*)(src + off + 4);
    uint4 u;
    u.x = pack_bf16(v0.x, v0.y);
    u.y = pack_bf16(v0.z, v0.w);
    u.z = pack_bf16(v1.x, v1.y);
    u.w = pack_bf16(v1.z, v1.w);
    *(uint4*)(dst + off) = u;
}

// ---------------------------------------------------------------------------
// Kernel 1: fused QKV projection, pure bf16, cp.async double-buffered, BK=64.
// ---------------------------------------------------------------------------
__global__ __launch_bounds__(256)
void qkv_gemm(const float* __restrict__ bq, const float* __restrict__ bk,
              const float* __restrict__ bv)
{
    extern __shared__ __nv_bfloat16 dsm[];
    __nv_bfloat16* Xs[2] = {dsm, dsm + 128 * 72};
    __nv_bfloat16* Ws[2] = {dsm + 2 * 128 * 72, dsm + 2 * 128 * 72 + 64 * 72};

    int z = blockIdx.z;
    const __nv_bfloat16* Xg = g_Xb;
    const __nv_bfloat16* Wg = g_Wb[z];
    const float* bias = (z == 0) ? bq : (z == 1) ? bk : bv;
    __nv_bfloat16* C = g_QKV[z];

    int row0 = blockIdx.y * 128;
    int col0 = blockIdx.x * 64;
    int tid  = threadIdx.x;
    int warp = tid >> 5, lane = tid & 31;
    int g = lane >> 2, t4 = lane & 3;
    int wm = (warp & 3) * 32;
    int wn = (warp >> 2) * 32;

    int a_r = ((lane >> 3) & 1) * 8 + (lane & 7);
    int a_c = (lane >> 4) * 8;
    int v_r = (lane & 7) + ((lane >> 3) & 1) * 8;
    int v_s = lane >> 4;

    int xrw[4], xce[4];
    #pragma unroll
    for (int it = 0; it < 4; ++it) {
        int c = tid + it * 256;
        xrw[it] = c >> 3; xce[it] = (c & 7) * 8;
    }
    int wrw[2], wce[2];
    #pragma unroll
    for (int it = 0; it < 2; ++it) {
        int c = tid + it * 256;
        wrw[it] = c >> 3; wce[it] = (c & 7) * 8;
    }

    auto stage = [&](int kit, int buf) {
        int k0 = kit * 64;
        #pragma unroll
        for (int it = 0; it < 4; ++it)
            cpa16(&Xs[buf][xrw[it] * 72 + xce[it]],
                  Xg + (size_t)(row0 + xrw[it]) * DD + k0 + xce[it]);
        #pragma unroll
        for (int it = 0; it < 2; ++it)
            cpa16(&Ws[buf][wrw[it] * 72 + wce[it]],
                  Wg + (size_t)(k0 + wrw[it]) * DD + col0 + wce[it]);
    };

    float acc[2][4][4] = {};

    stage(0, 0); CP_COMMIT;

    for (int it = 0; it < 8; ++it) {
        int buf = it & 1;
        if (it < 7) { stage(it + 1, buf ^ 1); CP_COMMIT; CP_WAIT1; }
        else        { CP_WAIT0; }
        __syncthreads();

        #pragma unroll
        for (int ch = 0; ch < 4; ++ch) {
            int kk = ch * 16;
            uint32_t a[2][4];
            ldm_x4(a[0], &Xs[buf][(wm + a_r) * 72 + kk + a_c]);
            ldm_x4(a[1], &Xs[buf][(wm + 16 + a_r) * 72 + kk + a_c]);
            uint32_t b0[4], b1[4];
            ldm_x4_trans(b0, &Ws[buf][(kk + v_r) * 72 + wn + v_s * 8]);
            ldm_x4_trans(b1, &Ws[buf][(kk + v_r) * 72 + wn + 16 + v_s * 8]);
            #pragma unroll
            for (int m = 0; m < 2; ++m) {
                mma16(acc[m][0], a[m], b0[0], b0[1], acc[m][0]);
                mma16(acc[m][1], a[m], b0[2], b0[3], acc[m][1]);
                mma16(acc[m][2], a[m], b1[0], b1[1], acc[m][2]);
                mma16(acc[m][3], a[m], b1[2], b1[3], acc[m][3]);
            }
        }
        __syncthreads();
    }

    #pragma unroll
    for (int n = 0; n < 4; ++n) {
        int col = col0 + wn + n * 8 + 2 * t4;
        float2 bb = *(const float2*)(bias + col);
        #pragma unroll
        for (int m = 0; m < 2; ++m) {
            int r0 = row0 + wm + m * 16 + g;
            *(uint32_t*)(C + (size_t)r0 * DD + col) =
                pack_bf16(acc[m][n][0] + bb.x, acc[m][n][1] + bb.y);
            *(uint32_t*)(C + (size_t)(r0 + 8) * DD + col) =
                pack_bf16(acc[m][n][2] + bb.x, acc[m][n][3] + bb.y);
        }
    }
}

// ---------------------------------------------------------------------------
// Kernel 2: c[row] = (x[row] . w_g[D:2D]) * log2e
// ---------------------------------------------------------------------------
__global__ __launch_bounds__(256)
void gate_kernel(const float* __restrict__ x, const float* __restrict__ wg)
{
    int row  = blockIdx.x * 8 + (threadIdx.x >> 5);
    int lane = threadIdx.x & 31;
    const float* xr = x + (size_t)row * DD;
    const float* w2 = wg + DD;
    float s = 0.f;
    #pragma unroll 4
    for (int d = lane; d < DD; d += 32) s = fmaf(xr[d], w2[d], s);
    #pragma unroll
    for (int off = 16; off > 0; off >>= 1)
        s += __shfl_xor_sync(0xffffffffu, s, off);
    if (lane == 0) g_c[row] = s * LOG2E;
}

// ---------------------------------------------------------------------------
// Kernel B1 (WIDE): blocks 0..127: per-(b,h) max ||k_j||^2 via block reduce +
// atomicMax on float bits. Blocks 128..129: per-batch max c_j.
// ---------------------------------------------------------------------------
__global__ __launch_bounds__(256)
void bounds_kernel()
{
    __shared__ float red[256];
    int blk = blockIdx.x, tid = threadIdx.x;
    float mx;
    if (blk < 128) {
        int bh = blk >> 3;                 // 0..15
        int j  = (blk & 7) * 256 + tid;    // row 0..2047
        int b = bh >> 3, h = bh & 7;
        const __nv_bfloat16* kr = g_QKV[1] + ((size_t)b * NN + j) * DD + h * HD;
        float s = 0.f;
        #pragma unroll
        for (int d = 0; d < HD; d += 8) {
            uint4 u = *(const uint4*)(kr + d);
            float2 f0 = __bfloat1622float2(*(__nv_bfloat162*)&u.x);
            float2 f1 = __bfloat1622float2(*(__nv_bfloat162*)&u.y);
            float2 f2 = __bfloat1622float2(*(__nv_bfloat162*)&u.z);
            float2 f3 = __bfloat1622float2(*(__nv_bfloat162*)&u.w);
            s = fmaf(f0.x, f0.x, fmaf(f0.y, f0.y, s));
            s = fmaf(f1.x, f1.x, fmaf(f1.y, f1.y, s));
            s = fmaf(f2.x, f2.x, fmaf(f2.y, f2.y, s));
            s = fmaf(f3.x, f3.x, fmaf(f3.y, f3.y, s));
        }
        mx = s;
        red[tid] = mx;
        __syncthreads();
        for (int st = 128; st > 0; st >>= 1) {
            if (tid < st) red[tid] = fmaxf(red[tid], red[tid + st]);
            __syncthreads();
        }
        if (tid == 0) atomicMax(&g_maxk_bits[bh], __float_as_uint(red[0]));
    } else {
        int b = blk - 128;
        mx = -1e30f;
        for (int j = tid; j < NN; j += 256)
            mx = fmaxf(mx, g_c[b * NN + j]);
        red[tid] = mx;
        __syncthreads();
        for (int st = 128; st > 0; st >>= 1) {
            if (tid < st) red[tid] = fmaxf(red[tid], red[tid + st]);
            __syncthreads();
        }
        if (tid == 0) atomicMax(&g_maxc_bits[b], enc_ord(red[0]));
    }
}

// ---------------------------------------------------------------------------
// Kernel 3: flash attention, bf16 mma. Each warp owns 32 query rows
// (2 m-tiles): every K/V ldmatrix feeds both m-tiles -> per-query smem
// crossbar traffic HALVES vs 16 rows/warp. Register pressure is kept in
// check by the static per-row exponent bound: S -> softmax -> PV is fused
// PER 16-KEY CHUNK, so only 16 S-registers are ever live (no 64-reg S tile,
// no online-softmax state). Triple-buffered cp.async, one barrier/iter,
// P in registers, one l reduction at the end.
// CTA = 128 queries (4 warps x 32 rows), 64-key tiles.
// ---------------------------------------------------------------------------
__global__ __launch_bounds__(128, 3)
void attn_kernel(const float* __restrict__ x, const float* __restrict__ adj,
                 float* __restrict__ out)
{
    extern __shared__ __nv_bfloat16 asm_buf[];
    const int TB = 64 * 72;
    __nv_bfloat16* Kb0 = asm_buf;            // K buffers 0..2
    __nv_bfloat16* Vb0 = asm_buf + 3 * TB;   // V buffers 0..2

    int tid  = threadIdx.x;
    int warp = tid >> 5, lane = tid & 31;
    int g = lane >> 2, t4 = lane & 3;
    int qr = warp * 32;                      // warp's 32-row query base
    int i0 = blockIdx.x * 128;
    int h  = blockIdx.y;
    int b  = blockIdx.z;

    int a_r = ((lane >> 3) & 1) * 8 + (lane & 7);   // A non-trans (Q)
    int a_c = (lane >> 4) * 8;
    int k_r = (lane >> 4) * 8 + (lane & 7);         // B non-trans (K)
    int k_c = ((lane >> 3) & 1) * 8;
    int v_r = (lane & 7) + ((lane >> 3) & 1) * 8;   // B trans (V)
    int v_s = lane >> 4;

    const __nv_bfloat16* Qg = g_QKV[0] + (size_t)b * NN * DD + h * HD;
    const __nv_bfloat16* Kg = g_QKV[1] + (size_t)b * NN * DD + h * HD;
    const __nv_bfloat16* Vg = g_QKV[2] + (size_t)b * NN * DD + h * HD;
    const float* cv   = g_c + b * NN;
    const float* adjb = adj + (size_t)b * NN * NN;

    int srw[4], sce[4];
    #pragma unroll
    for (int it = 0; it < 4; ++it) {
        int c = tid + it * 128;
        srw[it] = c >> 3; sce[it] = (c & 7) * 8;
    }

    auto stage_kv = [&](int jt, int buf) {
        int j0 = jt * 64;
        #pragma unroll
        for (int it = 0; it < 4; ++it) {
            cpa16(Kb0 + buf * TB + srw[it] * 72 + sce[it],
                  Kg + (size_t)(j0 + srw[it]) * DD + sce[it]);
            cpa16(Vb0 + buf * TB + srw[it] * 72 + sce[it],
                  Vg + (size_t)(j0 + srw[it]) * DD + sce[it]);
        }
    };

    // ---- Stage Q (128x64) into K buffers 1+2 (contiguous 18432 B) ----
    __nv_bfloat16* Qs = Kb0 + TB;
    #pragma unroll
    for (int it = 0; it < 8; ++it) {
        int c = tid + it * 128;
        int r = c >> 3, c8 = (c & 7) * 8;
        uint4 v = *(const uint4*)(Qg + (size_t)(i0 + r) * DD + c8);
        *(uint4*)&Qs[r * 72 + c8] = v;
    }
    stage_kv(0, 0); CP_COMMIT;
    __syncthreads();

    uint32_t qa[2][4][4];
    #pragma unroll
    for (int m = 0; m < 2; ++m)
        #pragma unroll
        for (int ch = 0; ch < 4; ++ch)
            ldm_x4(qa[m][ch], &Qs[(qr + m * 16 + a_r) * 72 + ch * 16 + a_c]);
    __syncthreads();   // all warps finished reading Q before iter-0 stages Kb1

    // ---- per-row ||q|| from fragments; static bounds ----
    float maxk = sqrtf(__uint_as_float(g_maxk_bits[b * HH + h]));
    float maxc = dec_ord(g_maxc_bits[b]);
    float mb[2][2];
    #pragma unroll
    for (int m = 0; m < 2; ++m) {
        float n0 = 0.f, n1 = 0.f;
        #pragma unroll
        for (int ch = 0; ch < 4; ++ch) {
            float2 f;
            f = __bfloat1622float2(*(__nv_bfloat162*)&qa[m][ch][0]);
            n0 = fmaf(f.x, f.x, fmaf(f.y, f.y, n0));
            f = __bfloat1622float2(*(__nv_bfloat162*)&qa[m][ch][2]);
            n0 = fmaf(f.x, f.x, fmaf(f.y, f.y, n0));
            f = __bfloat1622float2(*(__nv_bfloat162*)&qa[m][ch][1]);
            n1 = fmaf(f.x, f.x, fmaf(f.y, f.y, n1));
            f = __bfloat1622float2(*(__nv_bfloat162*)&qa[m][ch][3]);
            n1 = fmaf(f.x, f.x, fmaf(f.y, f.y, n1));
        }
        n0 += __shfl_xor_sync(0xffffffffu, n0, 1);
        n0 += __shfl_xor_sync(0xffffffffu, n0, 2);
        n1 += __shfl_xor_sync(0xffffffffu, n1, 1);
        n1 += __shfl_xor_sync(0xffffffffu, n1, 2);
        mb[m][0] = SCLOG * sqrtf(n0) * maxk + maxc + 1.0f;
        mb[m][1] = SCLOG * sqrtf(n1) * maxk + maxc + 1.0f;
    }

    float rs[2][2] = {};                 // per-thread l partials
    float o[2][8][4] = {};

    for (int jt = 0; jt < NN / 64; ++jt) {
        int j0 = jt * 64;
        int buf = jt % 3;
        if (jt + 1 < NN / 64) { stage_kv(jt + 1, (jt + 1) % 3); CP_COMMIT; CP_WAIT1; }
        else                  { CP_WAIT0; }
        __syncthreads();

        const __nv_bfloat16* Kt = Kb0 + buf * TB;
        const __nv_bfloat16* Vt = Vb0 + buf * TB;

        // ---- fused per-16-key-chunk: S -> p/pack -> PV ----
        #pragma unroll
        for (int ch = 0; ch < 4; ++ch) {
            // S for this chunk (2 n-tiles x 2 m-tiles), K-dim contraction
            float s2[2][2][4] = {};
            #pragma unroll
            for (int kch = 0; kch < 4; ++kch) {
                uint32_t kb[4];
                ldm_x4(kb, &Kt[(ch * 16 + k_r) * 72 + kch * 16 + k_c]);
                #pragma unroll
                for (int m = 0; m < 2; ++m) {
                    mma16(s2[m][0], qa[m][kch], kb[0], kb[1], s2[m][0]);
                    mma16(s2[m][1], qa[m][kch], kb[2], kb[3], s2[m][1]);
                }
            }

            // p = (adj+eps) * 2^(s*SC + c - m), packed into PV A-fragments
            uint32_t pac[2][4];
            #pragma unroll
            for (int m = 0; m < 2; ++m) {
                int r0 = i0 + qr + m * 16 + g, r1 = r0 + 8;
                #pragma unroll
                for (int w = 0; w < 2; ++w) {
                    int jc = j0 + ch * 16 + w * 8 + 2 * t4;
                    float2 cc = *(const float2*)(cv + jc);
                    float c0x = cc.x - mb[m][0], c0y = cc.y - mb[m][0];
                    float c1x = cc.x - mb[m][1], c1y = cc.y - mb[m][1];
                    float2 ad0 = *(const float2*)(adjb + (size_t)r0 * NN + jc);
                    float2 ad1 = *(const float2*)(adjb + (size_t)r1 * NN + jc);
                    float p00 = ex2f(fmaf(s2[m][w][0], SCLOG, c0x)) * (ad0.x + 1e-9f);
                    float p01 = ex2f(fmaf(s2[m][w][1], SCLOG, c0y)) * (ad0.y + 1e-9f);
                    float p10 = ex2f(fmaf(s2[m][w][2], SCLOG, c1x)) * (ad1.x + 1e-9f);
                    float p11 = ex2f(fmaf(s2[m][w][3], SCLOG, c1y)) * (ad1.y + 1e-9f);
                    rs[m][0] += p00 + p01; rs[m][1] += p10 + p11;
                    pac[m][2 * w]     = pack_bf16(p00, p01);
                    pac[m][2 * w + 1] = pack_bf16(p10, p11);
                }
            }

            // PV for this chunk; each V fragment feeds both m-tiles
            #pragma unroll
            for (int np = 0; np < 4; ++np) {
                uint32_t vb[4];
                ldm_x4_trans(vb, &Vt[(ch * 16 + v_r) * 72 + (2 * np + v_s) * 8]);
                #pragma unroll
                for (int m = 0; m < 2; ++m) {
                    mma16(o[m][2 * np],     pac[m], vb[0], vb[1], o[m][2 * np]);
                    mma16(o[m][2 * np + 1], pac[m], vb[2], vb[3], o[m][2 * np + 1]);
                }
            }
        }
    }

    // ---- l reduction (once) + epilogue: normalize + residual ----
    #pragma unroll
    for (int m = 0; m < 2; ++m) {
        rs[m][0] += __shfl_xor_sync(0xffffffffu, rs[m][0], 1);
        rs[m][0] += __shfl_xor_sync(0xffffffffu, rs[m][0], 2);
        rs[m][1] += __shfl_xor_sync(0xffffffffu, rs[m][1], 1);
        rs[m][1] += __shfl_xor_sync(0xffffffffu, rs[m][1], 2);
        float inv0 = __fdividef(1.0f, rs[m][0]);
        float inv1 = __fdividef(1.0f, rs[m][1]);
        int r0 = i0 + qr + m * 16 + g, r1 = r0 + 8;
        #pragma unroll
        for (int n = 0; n < 8; ++n) {
            int col = h * HD + n * 8 + 2 * t4;
            float2 x0 = *(const float2*)(x + ((size_t)b * NN + r0) * DD + col);
            float2 x1 = *(const float2*)(x + ((size_t)b * NN + r1) * DD + col);
            float2 o0 = {fmaf(o[m][n][0], inv0, x0.x), fmaf(o[m][n][1], inv0, x0.y)};
            float2 o1 = {fmaf(o[m][n][2], inv1, x1.x), fmaf(o[m][n][3], inv1, x1.y)};
            *(float2*)(out + ((size_t)b * NN + r0) * DD + col) = o0;
            *(float2*)(out + ((size_t)b * NN + r1) * DD + col) = o1;
        }
    }
}

// ---------------------------------------------------------------------------
extern "C" void kernel_launch(void* const* d_in, const int* in_sizes, int n_in,
                              void* d_out, int out_size)
{
    const float* x   = (const float*)d_in[0];
    const float* adj = (const float*)d_in[1];
    const float* Wq  = (const float*)d_in[2];
    const float* bq  = (const float*)d_in[3];
    const float* Wk  = (const float*)d_in[4];
    const float* bk  = (const float*)d_in[5];
    const float* Wv  = (const float*)d_in[6];
    const float* bv  = (const float*)d_in[7];
    const float* wg  = (const float*)d_in[8];
    // d_in[9] (b_g) cancels inside the softmax; unused.
    float* out = (float*)d_out;

    const int qkv_smem = (2 * 128 * 72 + 2 * 64 * 72) * 2;   // 55296 B
    cudaFuncSetAttribute((const void*)qkv_gemm,
                         cudaFuncAttributeMaxDynamicSharedMemorySize, qkv_smem);
    const int attn_smem = 6 * 64 * 72 * 2;                   // 55296 B
    cudaFuncSetAttribute((const void*)attn_kernel,
                         cudaFuncAttributeMaxDynamicSharedMemorySize, attn_smem);

    convert_kernel<<<1408, 256>>>(x, Wq, Wk, Wv);
    gate_kernel<<<ROWS / 8, 256>>>(x, wg);
    qkv_gemm<<<dim3(DD / 64, ROWS / 128, 3), 256, qkv_smem>>>(bq, bk, bv);
    bounds_kernel<<<130, 256>>>();
    attn_kernel<<<dim3(NN / 128, HH, BB), 128, attn_smem>>>(x, adj, out);
}

// round 12
// speedup vs baseline: 1.3583x; 1.3583x over previous
#include <cuda_runtime.h>
#include <cuda_bf16.h>
#include <cstdint>

#define BB 2
#define NN 2048
#define DD 512
#define HH 8
#define HD 64
#define ROWS (BB*NN)

// Scratch (no allocations allowed)
__device__ __nv_bfloat16 g_QKV[3][(size_t)ROWS * DD];   // Q,K,V projections
__device__ __nv_bfloat16 g_Xb[(size_t)ROWS * DD];       // x in bf16
__device__ __nv_bfloat16 g_Wb[3][(size_t)DD * DD];      // W_q/k/v in bf16
__device__ float g_c[ROWS];                             // gate vec (log2-scaled)
__device__ unsigned g_maxk_bits[BB * HH];               // max_j ||k_j||^2 (float bits)
__device__ unsigned g_maxc_bits[BB];                    // max_j c_j (monotone-encoded)

#define LOG2E 1.4426950408889634f
#define SCLOG (0.125f * LOG2E)

// ---------------------------------------------------------------------------
// helpers
// ---------------------------------------------------------------------------
__device__ __forceinline__ float ex2f(float x) {        // 2^x on MUFU
    float r;
    asm("ex2.approx.f32 %0, %1;" : "=f"(r) : "f"(x));
    return r;
}
__device__ __forceinline__ uint32_t pack_bf16(float lo, float hi) {
    uint32_t r;
    asm("cvt.rn.bf16x2.f32 %0, %1, %2;" : "=r"(r) : "f"(hi), "f"(lo));
    return r;
}
__device__ __forceinline__ unsigned enc_ord(float f) {  // monotone float->uint
    int i = __float_as_int(f);
    return (i < 0) ? ~(unsigned)i : ((unsigned)i | 0x80000000u);
}
__device__ __forceinline__ float dec_ord(unsigned u) {
    int i = (u & 0x80000000u) ? (int)(u & 0x7fffffffu) : (int)~u;
    return __int_as_float(i);
}
__device__ __forceinline__ void mma16(float* d, const uint32_t* a,
                                      uint32_t b0, uint32_t b1, const float* c) {
    asm("mma.sync.aligned.m16n8k16.row.col.f32.bf16.bf16.f32 "
        "{%0,%1,%2,%3}, {%4,%5,%6,%7}, {%8,%9}, {%10,%11,%12,%13};"
        : "=f"(d[0]), "=f"(d[1]), "=f"(d[2]), "=f"(d[3])
        : "r"(a[0]), "r"(a[1]), "r"(a[2]), "r"(a[3]),
          "r"(b0), "r"(b1),
          "f"(c[0]), "f"(c[1]), "f"(c[2]), "f"(c[3]));
}
__device__ __forceinline__ void ldm_x4(uint32_t* r, const void* ptr) {
    uint32_t a = (uint32_t)__cvta_generic_to_shared(ptr);
    asm volatile("ldmatrix.sync.aligned.m8n8.x4.shared.b16 "
                 "{%0,%1,%2,%3}, [%4];"
                 : "=r"(r[0]), "=r"(r[1]), "=r"(r[2]), "=r"(r[3]) : "r"(a));
}
__device__ __forceinline__ void ldm_x4_trans(uint32_t* r, const void* ptr) {
    uint32_t a = (uint32_t)__cvta_generic_to_shared(ptr);
    asm volatile("ldmatrix.sync.aligned.m8n8.x4.trans.shared.b16 "
                 "{%0,%1,%2,%3}, [%4];"
                 : "=r"(r[0]), "=r"(r[1]), "=r"(r[2]), "=r"(r[3]) : "r"(a));
}
__device__ __forceinline__ void cpa16(void* smem_dst, const void* gsrc) {
    uint32_t d = (uint32_t)__cvta_generic_to_shared(smem_dst);
    asm volatile("cp.async.cg.shared.global [%0], [%1], 16;" :: "r"(d), "l"(gsrc));
}
#define CP_COMMIT asm volatile("cp.async.commit_group;" ::: "memory")
#define CP_WAIT1  asm volatile("cp.async.wait_group 1;" ::: "memory")
#define CP_WAIT0  asm volatile("cp.async.wait_group 0;" ::: "memory")

// ---------------------------------------------------------------------------
// Kernel 0: one-shot fp32 -> bf16 conversion of x and W_q/k/v.
// Also resets the bound atomics (block 0) — runs first every graph replay.
// ---------------------------------------------------------------------------
__global__ __launch_bounds__(256)
void convert_kernel(const float* __restrict__ X, const float* __restrict__ Wq,
                    const float* __restrict__ Wk, const float* __restrict__ Wv)
{
    if (blockIdx.x == 0) {
        int t = threadIdx.x;
        if (t < BB * HH) g_maxk_bits[t] = 0u;             // ||k||^2 >= 0
        if (t < BB)      g_maxc_bits[t] = 0u;             // encodes very-negative
    }
    int idx = blockIdx.x * 256 + threadIdx.x;
    const float* src;
    __nv_bfloat16* dst;
    size_t off;
    if (idx < 262144) {
        src = X; dst = g_Xb; off = (size_t)idx * 8;
    } else {
        int r = idx - 262144;
        int z = r >> 15;
        int o = r & 32767;
        src = (z == 0) ? Wq : (z == 1) ? Wk : Wv;
        dst = g_Wb[z]; off = (size_t)o * 8;
    }
    float4 v0 = *(const float4*)(src + off);
    float4 v1 = *(const float4*)(src + off + 4);
    uint4 u;
    u.x = pack_bf16(v0.x, v0.y);
    u.y = pack_bf16(v0.z, v0.w);
    u.z = pack_bf16(v1.x, v1.y);
    u.w = pack_bf16(v1.z, v1.w);
    *(uint4*)(dst + off) = u;
}

// ---------------------------------------------------------------------------
// Kernel 1: fused QKV projection, pure bf16, cp.async double-buffered, BK=64.
// ---------------------------------------------------------------------------
__global__ __launch_bounds__(256)
void qkv_gemm(const float* __restrict__ bq, const float* __restrict__ bk,
              const float* __restrict__ bv)
{
    extern __shared__ __nv_bfloat16 dsm[];
    __nv_bfloat16* Xs[2] = {dsm, dsm + 128 * 72};
    __nv_bfloat16* Ws[2] = {dsm + 2 * 128 * 72, dsm + 2 * 128 * 72 + 64 * 72};

    int z = blockIdx.z;
    const __nv_bfloat16* Xg = g_Xb;
    const __nv_bfloat16* Wg = g_Wb[z];
    const float* bias = (z == 0) ? bq : (z == 1) ? bk : bv;
    __nv_bfloat16* C = g_QKV[z];

    int row0 = blockIdx.y * 128;
    int col0 = blockIdx.x * 64;
    int tid  = threadIdx.x;
    int warp = tid >> 5, lane = tid & 31;
    int g = lane >> 2, t4 = lane & 3;
    int wm = (warp & 3) * 32;
    int wn = (warp >> 2) * 32;

    int a_r = ((lane >> 3) & 1) * 8 + (lane & 7);
    int a_c = (lane >> 4) * 8;
    int v_r = (lane & 7) + ((lane >> 3) & 1) * 8;
    int v_s = lane >> 4;

    int xrw[4], xce[4];
    #pragma unroll
    for (int it = 0; it < 4; ++it) {
        int c = tid + it * 256;
        xrw[it] = c >> 3; xce[it] = (c & 7) * 8;
    }
    int wrw[2], wce[2];
    #pragma unroll
    for (int it = 0; it < 2; ++it) {
        int c = tid + it * 256;
        wrw[it] = c >> 3; wce[it] = (c & 7) * 8;
    }

    auto stage = [&](int kit, int buf) {
        int k0 = kit * 64;
        #pragma unroll
        for (int it = 0; it < 4; ++it)
            cpa16(&Xs[buf][xrw[it] * 72 + xce[it]],
                  Xg + (size_t)(row0 + xrw[it]) * DD + k0 + xce[it]);
        #pragma unroll
        for (int it = 0; it < 2; ++it)
            cpa16(&Ws[buf][wrw[it] * 72 + wce[it]],
                  Wg + (size_t)(k0 + wrw[it]) * DD + col0 + wce[it]);
    };

    float acc[2][4][4] = {};

    stage(0, 0); CP_COMMIT;

    for (int it = 0; it < 8; ++it) {
        int buf = it & 1;
        if (it < 7) { stage(it + 1, buf ^ 1); CP_COMMIT; CP_WAIT1; }
        else        { CP_WAIT0; }
        __syncthreads();

        #pragma unroll
        for (int ch = 0; ch < 4; ++ch) {
            int kk = ch * 16;
            uint32_t a[2][4];
            ldm_x4(a[0], &Xs[buf][(wm + a_r) * 72 + kk + a_c]);
            ldm_x4(a[1], &Xs[buf][(wm + 16 + a_r) * 72 + kk + a_c]);
            uint32_t b0[4], b1[4];
            ldm_x4_trans(b0, &Ws[buf][(kk + v_r) * 72 + wn + v_s * 8]);
            ldm_x4_trans(b1, &Ws[buf][(kk + v_r) * 72 + wn + 16 + v_s * 8]);
            #pragma unroll
            for (int m = 0; m < 2; ++m) {
                mma16(acc[m][0], a[m], b0[0], b0[1], acc[m][0]);
                mma16(acc[m][1], a[m], b0[2], b0[3], acc[m][1]);
                mma16(acc[m][2], a[m], b1[0], b1[1], acc[m][2]);
                mma16(acc[m][3], a[m], b1[2], b1[3], acc[m][3]);
            }
        }
        __syncthreads();
    }

    #pragma unroll
    for (int n = 0; n < 4; ++n) {
        int col = col0 + wn + n * 8 + 2 * t4;
        float2 bb = *(const float2*)(bias + col);
        #pragma unroll
        for (int m = 0; m < 2; ++m) {
            int r0 = row0 + wm + m * 16 + g;
            *(uint32_t*)(C + (size_t)r0 * DD + col) =
                pack_bf16(acc[m][n][0] + bb.x, acc[m][n][1] + bb.y);
            *(uint32_t*)(C + (size_t)(r0 + 8) * DD + col) =
                pack_bf16(acc[m][n][2] + bb.x, acc[m][n][3] + bb.y);
        }
    }
}

// ---------------------------------------------------------------------------
// Kernel 2: c[row] = (x[row] . w_g[D:2D]) * log2e. Also folds the per-batch
// max_j c_j into g_maxc_bits (block max + one atomicMax per block; each
// block's 8 rows lie in one batch since 8 | 2048).
// ---------------------------------------------------------------------------
__global__ __launch_bounds__(256)
void gate_kernel(const float* __restrict__ x, const float* __restrict__ wg)
{
    __shared__ float cmax[8];
    int row  = blockIdx.x * 8 + (threadIdx.x >> 5);
    int warp = threadIdx.x >> 5;
    int lane = threadIdx.x & 31;
    const float* xr = x + (size_t)row * DD;
    const float* w2 = wg + DD;
    float s = 0.f;
    #pragma unroll 4
    for (int d = lane; d < DD; d += 32) s = fmaf(xr[d], w2[d], s);
    #pragma unroll
    for (int off = 16; off > 0; off >>= 1)
        s += __shfl_xor_sync(0xffffffffu, s, off);
    s *= LOG2E;
    if (lane == 0) { g_c[row] = s; cmax[warp] = s; }
    __syncthreads();
    if (threadIdx.x == 0) {
        float m = cmax[0];
        #pragma unroll
        for (int i = 1; i < 8; ++i) m = fmaxf(m, cmax[i]);
        atomicMax(&g_maxc_bits[row >> 11], enc_ord(m));
    }
}

// ---------------------------------------------------------------------------
// Kernel B1: per-(b,h) max ||k_j||^2. 128 blocks x 256 threads = one thread
// per (bh, row). Pure warp-shuffle reduce + one atomicMax per warp — no
// block tree, no barriers.
// ---------------------------------------------------------------------------
__global__ __launch_bounds__(256)
void knorm_kernel()
{
    int blk = blockIdx.x, tid = threadIdx.x;
    int bh = blk >> 3;                 // 0..15
    int j  = (blk & 7) * 256 + tid;    // row 0..2047
    int b = bh >> 3, h = bh & 7;
    const __nv_bfloat16* kr = g_QKV[1] + ((size_t)b * NN + j) * DD + h * HD;
    float s = 0.f;
    #pragma unroll
    for (int d = 0; d < HD; d += 8) {
        uint4 u = *(const uint4*)(kr + d);
        float2 f0 = __bfloat1622float2(*(__nv_bfloat162*)&u.x);
        float2 f1 = __bfloat1622float2(*(__nv_bfloat162*)&u.y);
        float2 f2 = __bfloat1622float2(*(__nv_bfloat162*)&u.z);
        float2 f3 = __bfloat1622float2(*(__nv_bfloat162*)&u.w);
        s = fmaf(f0.x, f0.x, fmaf(f0.y, f0.y, s));
        s = fmaf(f1.x, f1.x, fmaf(f1.y, f1.y, s));
        s = fmaf(f2.x, f2.x, fmaf(f2.y, f2.y, s));
        s = fmaf(f3.x, f3.x, fmaf(f3.y, f3.y, s));
    }
    #pragma unroll
    for (int off = 16; off > 0; off >>= 1)
        s = fmaxf(s, __shfl_xor_sync(0xffffffffu, s, off));
    if ((tid & 31) == 0)
        atomicMax(&g_maxk_bits[bh], __float_as_uint(s));
}

// ---------------------------------------------------------------------------
// Kernel 3: flash attention, bf16 mma, triple-buffered cp.async, P in
// registers, static per-row exponent bound (no online softmax). Mainloop is
// fused PER 16-KEY CHUNK (S -> p/pack -> PV) so only 8 S-registers are ever
// live: regs ~100 at occ 4. FP accumulation order identical to the unfused
// version. CTA = (64-query tile, h, b), 128 threads = 4 warps x 16 rows.
// ---------------------------------------------------------------------------
__global__ __launch_bounds__(128, 4)
void attn_kernel(const float* __restrict__ x, const float* __restrict__ adj,
                 float* __restrict__ out)
{
    extern __shared__ __nv_bfloat16 asm_buf[];
    const int TB = 64 * 72;
    __nv_bfloat16* Kb0 = asm_buf;            // K buffers 0..2
    __nv_bfloat16* Vb0 = asm_buf + 3 * TB;   // V buffers 0..2

    int tid  = threadIdx.x;
    int warp = tid >> 5, lane = tid & 31;
    int g = lane >> 2, t4 = lane & 3;
    int qr = warp * 16;
    int i0 = blockIdx.x * 64;
    int h  = blockIdx.y;
    int b  = blockIdx.z;

    int a_r = ((lane >> 3) & 1) * 8 + (lane & 7);   // A non-trans (Q)
    int a_c = (lane >> 4) * 8;
    int k_r = (lane >> 4) * 8 + (lane & 7);         // B non-trans (K)
    int k_c = ((lane >> 3) & 1) * 8;
    int v_r = (lane & 7) + ((lane >> 3) & 1) * 8;   // B trans (V)
    int v_s = lane >> 4;

    const __nv_bfloat16* Qg = g_QKV[0] + (size_t)b * NN * DD + h * HD;
    const __nv_bfloat16* Kg = g_QKV[1] + (size_t)b * NN * DD + h * HD;
    const __nv_bfloat16* Vg = g_QKV[2] + (size_t)b * NN * DD + h * HD;
    const float* cv   = g_c + b * NN;
    const float* adjb = adj + (size_t)b * NN * NN;

    int srw[4], sce[4];
    #pragma unroll
    for (int it = 0; it < 4; ++it) {
        int c = tid + it * 128;
        srw[it] = c >> 3; sce[it] = (c & 7) * 8;
    }

    auto stage_kv = [&](int jt, int buf) {
        int j0 = jt * 64;
        #pragma unroll
        for (int it = 0; it < 4; ++it) {
            cpa16(Kb0 + buf * TB + srw[it] * 72 + sce[it],
                  Kg + (size_t)(j0 + srw[it]) * DD + sce[it]);
            cpa16(Vb0 + buf * TB + srw[it] * 72 + sce[it],
                  Vg + (size_t)(j0 + srw[it]) * DD + sce[it]);
        }
    };

    // ---- Stage Q into V buffer 2 (free until iter 1's staging) ----
    __nv_bfloat16* Qs = Vb0 + 2 * TB;
    #pragma unroll
    for (int it = 0; it < 4; ++it) {
        uint4 v = *(const uint4*)(Qg + (size_t)(i0 + srw[it]) * DD + sce[it]);
        *(uint4*)&Qs[srw[it] * 72 + sce[it]] = v;
    }
    stage_kv(0, 0); CP_COMMIT;
    __syncthreads();

    uint32_t qa[4][4];
    #pragma unroll
    for (int ch = 0; ch < 4; ++ch)
        ldm_x4(qa[ch], &Qs[(qr + a_r) * 72 + ch * 16 + a_c]);
    // iter-0's block barrier protects Qs before iter-1 stages buffer 2.

    // ---- per-row ||q|| from fragments (rows live in 4-lane groups) ----
    float nq0 = 0.f, nq1 = 0.f;
    #pragma unroll
    for (int ch = 0; ch < 4; ++ch) {
        float2 f;
        f = __bfloat1622float2(*(__nv_bfloat162*)&qa[ch][0]);
        nq0 = fmaf(f.x, f.x, fmaf(f.y, f.y, nq0));
        f = __bfloat1622float2(*(__nv_bfloat162*)&qa[ch][2]);
        nq0 = fmaf(f.x, f.x, fmaf(f.y, f.y, nq0));
        f = __bfloat1622float2(*(__nv_bfloat162*)&qa[ch][1]);
        nq1 = fmaf(f.x, f.x, fmaf(f.y, f.y, nq1));
        f = __bfloat1622float2(*(__nv_bfloat162*)&qa[ch][3]);
        nq1 = fmaf(f.x, f.x, fmaf(f.y, f.y, nq1));
    }
    nq0 += __shfl_xor_sync(0xffffffffu, nq0, 1);
    nq0 += __shfl_xor_sync(0xffffffffu, nq0, 2);
    nq1 += __shfl_xor_sync(0xffffffffu, nq1, 1);
    nq1 += __shfl_xor_sync(0xffffffffu, nq1, 2);

    float maxk = sqrtf(__uint_as_float(g_maxk_bits[b * HH + h]));
    float maxc = dec_ord(g_maxc_bits[b]);
    float m0 = SCLOG * sqrtf(nq0) * maxk + maxc + 1.0f;
    float m1 = SCLOG * sqrtf(nq1) * maxk + maxc + 1.0f;

    int r0g = i0 + qr + g, r1g = r0g + 8;
    float rs0 = 0.f, rs1 = 0.f;   // per-thread l partials across ALL iterations
    float o[8][4] = {};

    for (int jt = 0; jt < NN / 64; ++jt) {
        int j0 = jt * 64;
        int buf = jt % 3;
        if (jt + 1 < NN / 64) { stage_kv(jt + 1, (jt + 1) % 3); CP_COMMIT; CP_WAIT1; }
        else                  { CP_WAIT0; }
        __syncthreads();

        const __nv_bfloat16* Kt = Kb0 + buf * TB;
        const __nv_bfloat16* Vt = Vb0 + buf * TB;

        // ---- fused per-16-key chunk: S -> p/pack -> PV ----
        #pragma unroll
        for (int ch = 0; ch < 4; ++ch) {
            // S for key chunk ch (n-tiles 2ch, 2ch+1), contraction over k
            float s2[2][4] = {};
            #pragma unroll
            for (int kch = 0; kch < 4; ++kch) {
                uint32_t kb[4];
                ldm_x4(kb, &Kt[(ch * 16 + k_r) * 72 + kch * 16 + k_c]);
                mma16(s2[0], qa[kch], kb[0], kb[1], s2[0]);
                mma16(s2[1], qa[kch], kb[2], kb[3], s2[1]);
            }

            // p = (adj+eps) * 2^(s*SC + c - m), packed into PV A-fragment
            uint32_t pac[4];
            #pragma unroll
            for (int w = 0; w < 2; ++w) {
                int jc = j0 + ch * 16 + w * 8 + 2 * t4;
                float2 cc = *(const float2*)(cv + jc);
                float c0x = cc.x - m0, c0y = cc.y - m0;
                float c1x = cc.x - m1, c1y = cc.y - m1;
                float2 ad0 = *(const float2*)(adjb + (size_t)r0g * NN + jc);
                float2 ad1 = *(const float2*)(adjb + (size_t)r1g * NN + jc);
                float p00 = ex2f(fmaf(s2[w][0], SCLOG, c0x)) * (ad0.x + 1e-9f);
                float p01 = ex2f(fmaf(s2[w][1], SCLOG, c0y)) * (ad0.y + 1e-9f);
                float p10 = ex2f(fmaf(s2[w][2], SCLOG, c1x)) * (ad1.x + 1e-9f);
                float p11 = ex2f(fmaf(s2[w][3], SCLOG, c1y)) * (ad1.y + 1e-9f);
                rs0 += p00 + p01; rs1 += p10 + p11;
                pac[2 * w]     = pack_bf16(p00, p01);
                pac[2 * w + 1] = pack_bf16(p10, p11);
            }

            // PV for this key chunk
            #pragma unroll
            for (int np = 0; np < 4; ++np) {
                uint32_t vb[4];
                ldm_x4_trans(vb, &Vt[(ch * 16 + v_r) * 72 + (2 * np + v_s) * 8]);
                mma16(o[2 * np],     pac, vb[0], vb[1], o[2 * np]);
                mma16(o[2 * np + 1], pac, vb[2], vb[3], o[2 * np + 1]);
            }
        }
    }

    // ---- single end-of-kernel l reduction ----
    rs0 += __shfl_xor_sync(0xffffffffu, rs0, 1);
    rs0 += __shfl_xor_sync(0xffffffffu, rs0, 2);
    rs1 += __shfl_xor_sync(0xffffffffu, rs1, 1);
    rs1 += __shfl_xor_sync(0xffffffffu, rs1, 2);

    // ---- epilogue: normalize + residual (fp32) ----
    float inv0 = __fdividef(1.0f, rs0);
    float inv1 = __fdividef(1.0f, rs1);
    #pragma unroll
    for (int n = 0; n < 8; ++n) {
        int col = h * HD + n * 8 + 2 * t4;
        float2 x0 = *(const float2*)(x + ((size_t)b * NN + r0g) * DD + col);
        float2 x1 = *(const float2*)(x + ((size_t)b * NN + r1g) * DD + col);
        float2 o0 = {fmaf(o[n][0], inv0, x0.x), fmaf(o[n][1], inv0, x0.y)};
        float2 o1 = {fmaf(o[n][2], inv1, x1.x), fmaf(o[n][3], inv1, x1.y)};
        *(float2*)(out + ((size_t)b * NN + r0g) * DD + col) = o0;
        *(float2*)(out + ((size_t)b * NN + r1g) * DD + col) = o1;
    }
}

// ---------------------------------------------------------------------------
extern "C" void kernel_launch(void* const* d_in, const int* in_sizes, int n_in,
                              void* d_out, int out_size)
{
    const float* x   = (const float*)d_in[0];
    const float* adj = (const float*)d_in[1];
    const float* Wq  = (const float*)d_in[2];
    const float* bq  = (const float*)d_in[3];
    const float* Wk  = (const float*)d_in[4];
    const float* bk  = (const float*)d_in[5];
    const float* Wv  = (const float*)d_in[6];
    const float* bv  = (const float*)d_in[7];
    const float* wg  = (const float*)d_in[8];
    // d_in[9] (b_g) cancels inside the softmax; unused.
    float* out = (float*)d_out;

    const int qkv_smem = (2 * 128 * 72 + 2 * 64 * 72) * 2;   // 55296 B
    cudaFuncSetAttribute((const void*)qkv_gemm,
                         cudaFuncAttributeMaxDynamicSharedMemorySize, qkv_smem);
    const int attn_smem = 6 * 64 * 72 * 2;                   // 55296 B
    cudaFuncSetAttribute((const void*)attn_kernel,
                         cudaFuncAttributeMaxDynamicSharedMemorySize, attn_smem);

    convert_kernel<<<1408, 256>>>(x, Wq, Wk, Wv);
    gate_kernel<<<ROWS / 8, 256>>>(x, wg);
    qkv_gemm<<<dim3(DD / 64, ROWS / 128, 3), 256, qkv_smem>>>(bq, bk, bv);
    knorm_kernel<<<128, 256>>>();
    attn_kernel<<<dim3(NN / 64, HH, BB), 128, attn_smem>>>(x, adj, out);
}

// round 13
// speedup vs baseline: 1.3818x; 1.0173x over previous
#include <cuda_runtime.h>
#include <cuda_bf16.h>
#include <cstdint>

#define BB 2
#define NN 2048
#define DD 512
#define HH 8
#define HD 64
#define ROWS (BB*NN)

// Scratch (no allocations allowed)
__device__ __nv_bfloat16 g_QKV[3][(size_t)ROWS * DD];   // Q,K,V projections
__device__ __nv_bfloat16 g_Xb[(size_t)ROWS * DD];       // x in bf16
__device__ __nv_bfloat16 g_Wb[3][(size_t)DD * DD];      // W_q/k/v in bf16
__device__ float g_c[ROWS];                             // gate vec (log2-scaled)
__device__ unsigned g_maxk_bits[BB * HH];               // max_j ||k_j||^2 (float bits)
__device__ unsigned g_maxc_bits[BB];                    // max_j c_j (monotone-encoded)

#define LOG2E 1.4426950408889634f
#define SCLOG (0.125f * LOG2E)

// ---------------------------------------------------------------------------
// helpers
// ---------------------------------------------------------------------------
__device__ __forceinline__ float ex2f(float x) {        // 2^x on MUFU
    float r;
    asm("ex2.approx.f32 %0, %1;" : "=f"(r) : "f"(x));
    return r;
}
__device__ __forceinline__ uint32_t pack_bf16(float lo, float hi) {
    uint32_t r;
    asm("cvt.rn.bf16x2.f32 %0, %1, %2;" : "=r"(r) : "f"(hi), "f"(lo));
    return r;
}
__device__ __forceinline__ unsigned enc_ord(float f) {  // monotone float->uint
    int i = __float_as_int(f);
    return (i < 0) ? ~(unsigned)i : ((unsigned)i | 0x80000000u);
}
__device__ __forceinline__ float dec_ord(unsigned u) {
    int i = (u & 0x80000000u) ? (int)(u & 0x7fffffffu) : (int)~u;
    return __int_as_float(i);
}
__device__ __forceinline__ void mma16(float* d, const uint32_t* a,
                                      uint32_t b0, uint32_t b1, const float* c) {
    asm("mma.sync.aligned.m16n8k16.row.col.f32.bf16.bf16.f32 "
        "{%0,%1,%2,%3}, {%4,%5,%6,%7}, {%8,%9}, {%10,%11,%12,%13};"
        : "=f"(d[0]), "=f"(d[1]), "=f"(d[2]), "=f"(d[3])
        : "r"(a[0]), "r"(a[1]), "r"(a[2]), "r"(a[3]),
          "r"(b0), "r"(b1),
          "f"(c[0]), "f"(c[1]), "f"(c[2]), "f"(c[3]));
}
__device__ __forceinline__ void ldm_x4(uint32_t* r, const void* ptr) {
    uint32_t a = (uint32_t)__cvta_generic_to_shared(ptr);
    asm volatile("ldmatrix.sync.aligned.m8n8.x4.shared.b16 "
                 "{%0,%1,%2,%3}, [%4];"
                 : "=r"(r[0]), "=r"(r[1]), "=r"(r[2]), "=r"(r[3]) : "r"(a));
}
__device__ __forceinline__ void ldm_x4_trans(uint32_t* r, const void* ptr) {
    uint32_t a = (uint32_t)__cvta_generic_to_shared(ptr);
    asm volatile("ldmatrix.sync.aligned.m8n8.x4.trans.shared.b16 "
                 "{%0,%1,%2,%3}, [%4];"
                 : "=r"(r[0]), "=r"(r[1]), "=r"(r[2]), "=r"(r[3]) : "r"(a));
}
__device__ __forceinline__ void cpa16(void* smem_dst, const void* gsrc) {
    uint32_t d = (uint32_t)__cvta_generic_to_shared(smem_dst);
    asm volatile("cp.async.cg.shared.global [%0], [%1], 16;" :: "r"(d), "l"(gsrc));
}
#define CP_COMMIT asm volatile("cp.async.commit_group;" ::: "memory")
#define CP_WAIT1  asm volatile("cp.async.wait_group 1;" ::: "memory")
#define CP_WAIT0  asm volatile("cp.async.wait_group 0;" ::: "memory")

// ---------------------------------------------------------------------------
// Kernel 0: one-shot fp32 -> bf16 conversion of x and W_q/k/v.
// Also resets the bound atomics (block 0) — runs first every graph replay.
// ---------------------------------------------------------------------------
__global__ __launch_bounds__(256)
void convert_kernel(const float* __restrict__ X, const float* __restrict__ Wq,
                    const float* __restrict__ Wk, const float* __restrict__ Wv)
{
    if (blockIdx.x == 0) {
        int t = threadIdx.x;
        if (t < BB * HH) g_maxk_bits[t] = 0u;             // ||k||^2 >= 0
        if (t < BB)      g_maxc_bits[t] = 0u;             // encodes very-negative
    }
    int idx = blockIdx.x * 256 + threadIdx.x;
    const float* src;
    __nv_bfloat16* dst;
    size_t off;
    if (idx < 262144) {
        src = X; dst = g_Xb; off = (size_t)idx * 8;
    } else {
        int r = idx - 262144;
        int z = r >> 15;
        int o = r & 32767;
        src = (z == 0) ? Wq : (z == 1) ? Wk : Wv;
        dst = g_Wb[z]; off = (size_t)o * 8;
    }
    float4 v0 = *(const float4*)(src + off);
    float4 v1 = *(const float4*)(src + off + 4);
    uint4 u;
    u.x = pack_bf16(v0.x, v0.y);
    u.y = pack_bf16(v0.z, v0.w);
    u.z = pack_bf16(v1.x, v1.y);
    u.w = pack_bf16(v1.z, v1.w);
    *(uint4*)(dst + off) = u;
}

// ---------------------------------------------------------------------------
// Kernel 1: fused QKV projection, pure bf16, cp.async double-buffered, BK=64.
// z==1 (K) CTAs also fold the per-(b,h) max ||k||^2 bound into g_maxk_bits
// in the epilogue (each CTA covers 128 rows x exactly one 64-dim head).
// ---------------------------------------------------------------------------
__global__ __launch_bounds__(256)
void qkv_gemm(const float* __restrict__ bq, const float* __restrict__ bk,
              const float* __restrict__ bv)
{
    extern __shared__ __nv_bfloat16 dsm[];
    __nv_bfloat16* Xs[2] = {dsm, dsm + 128 * 72};
    __nv_bfloat16* Ws[2] = {dsm + 2 * 128 * 72, dsm + 2 * 128 * 72 + 64 * 72};

    int z = blockIdx.z;
    const __nv_bfloat16* Xg = g_Xb;
    const __nv_bfloat16* Wg = g_Wb[z];
    const float* bias = (z == 0) ? bq : (z == 1) ? bk : bv;
    __nv_bfloat16* C = g_QKV[z];

    int row0 = blockIdx.y * 128;
    int col0 = blockIdx.x * 64;
    int tid  = threadIdx.x;
    int warp = tid >> 5, lane = tid & 31;
    int g = lane >> 2, t4 = lane & 3;
    int wm = (warp & 3) * 32;
    int wn = (warp >> 2) * 32;

    int a_r = ((lane >> 3) & 1) * 8 + (lane & 7);
    int a_c = (lane >> 4) * 8;
    int v_r = (lane & 7) + ((lane >> 3) & 1) * 8;
    int v_s = lane >> 4;

    int xrw[4], xce[4];
    #pragma unroll
    for (int it = 0; it < 4; ++it) {
        int c = tid + it * 256;
        xrw[it] = c >> 3; xce[it] = (c & 7) * 8;
    }
    int wrw[2], wce[2];
    #pragma unroll
    for (int it = 0; it < 2; ++it) {
        int c = tid + it * 256;
        wrw[it] = c >> 3; wce[it] = (c & 7) * 8;
    }

    auto stage = [&](int kit, int buf) {
        int k0 = kit * 64;
        #pragma unroll
        for (int it = 0; it < 4; ++it)
            cpa16(&Xs[buf][xrw[it] * 72 + xce[it]],
                  Xg + (size_t)(row0 + xrw[it]) * DD + k0 + xce[it]);
        #pragma unroll
        for (int it = 0; it < 2; ++it)
            cpa16(&Ws[buf][wrw[it] * 72 + wce[it]],
                  Wg + (size_t)(k0 + wrw[it]) * DD + col0 + wce[it]);
    };

    float acc[2][4][4] = {};

    stage(0, 0); CP_COMMIT;

    for (int it = 0; it < 8; ++it) {
        int buf = it & 1;
        if (it < 7) { stage(it + 1, buf ^ 1); CP_COMMIT; CP_WAIT1; }
        else        { CP_WAIT0; }
        __syncthreads();

        #pragma unroll
        for (int ch = 0; ch < 4; ++ch) {
            int kk = ch * 16;
            uint32_t a[2][4];
            ldm_x4(a[0], &Xs[buf][(wm + a_r) * 72 + kk + a_c]);
            ldm_x4(a[1], &Xs[buf][(wm + 16 + a_r) * 72 + kk + a_c]);
            uint32_t b0[4], b1[4];
            ldm_x4_trans(b0, &Ws[buf][(kk + v_r) * 72 + wn + v_s * 8]);
            ldm_x4_trans(b1, &Ws[buf][(kk + v_r) * 72 + wn + 16 + v_s * 8]);
            #pragma unroll
            for (int m = 0; m < 2; ++m) {
                mma16(acc[m][0], a[m], b0[0], b0[1], acc[m][0]);
                mma16(acc[m][1], a[m], b0[2], b0[3], acc[m][1]);
                mma16(acc[m][2], a[m], b1[0], b1[1], acc[m][2]);
                mma16(acc[m][3], a[m], b1[2], b1[3], acc[m][3]);
            }
        }
        __syncthreads();
    }

    // epilogue: + bias (in-place), pack to bf16, store
    #pragma unroll
    for (int n = 0; n < 4; ++n) {
        int col = col0 + wn + n * 8 + 2 * t4;
        float2 bb = *(const float2*)(bias + col);
        #pragma unroll
        for (int m = 0; m < 2; ++m) {
            int r0 = row0 + wm + m * 16 + g;
            acc[m][n][0] += bb.x; acc[m][n][1] += bb.y;
            acc[m][n][2] += bb.x; acc[m][n][3] += bb.y;
            *(uint32_t*)(C + (size_t)r0 * DD + col) =
                pack_bf16(acc[m][n][0], acc[m][n][1]);
            *(uint32_t*)(C + (size_t)(r0 + 8) * DD + col) =
                pack_bf16(acc[m][n][2], acc[m][n][3]);
        }
    }

    // ---- K-norm bound fold (z==1 only): max_row ||K_row||^2 for this head ----
    if (z == 1) {
        float* rn = (float*)dsm;          // reuse smem (post-barrier above)
        if (tid < 128) rn[tid] = 0.f;
        __syncthreads();
        #pragma unroll
        for (int m = 0; m < 2; ++m) {
            float s0 = 0.f, s1 = 0.f;     // rows wm+m*16+g and +8 (this warp's 32 cols)
            #pragma unroll
            for (int n = 0; n < 4; ++n) {
                s0 = fmaf(acc[m][n][0], acc[m][n][0],
                     fmaf(acc[m][n][1], acc[m][n][1], s0));
                s1 = fmaf(acc[m][n][2], acc[m][n][2],
                     fmaf(acc[m][n][3], acc[m][n][3], s1));
            }
            s0 += __shfl_xor_sync(0xffffffffu, s0, 1);
            s0 += __shfl_xor_sync(0xffffffffu, s0, 2);
            s1 += __shfl_xor_sync(0xffffffffu, s1, 1);
            s1 += __shfl_xor_sync(0xffffffffu, s1, 2);
            if (t4 == 0) {
                atomicAdd(&rn[wm + m * 16 + g], s0);
                atomicAdd(&rn[wm + m * 16 + 8 + g], s1);
            }
        }
        __syncthreads();
        if (tid < 128) {
            float v = rn[tid];
            #pragma unroll
            for (int off = 16; off > 0; off >>= 1)
                v = fmaxf(v, __shfl_xor_sync(0xffffffffu, v, off));
            if ((tid & 31) == 0) {
                int bh = (row0 >= NN ? HH : 0) + (col0 >> 6);
                atomicMax(&g_maxk_bits[bh], __float_as_uint(v));
            }
        }
    }
}

// ---------------------------------------------------------------------------
// Kernel 2: c[row] = (x[row] . w_g[D:2D]) * log2e; folds per-batch max c.
// ---------------------------------------------------------------------------
__global__ __launch_bounds__(256)
void gate_kernel(const float* __restrict__ x, const float* __restrict__ wg)
{
    __shared__ float cmax[8];
    int row  = blockIdx.x * 8 + (threadIdx.x >> 5);
    int warp = threadIdx.x >> 5;
    int lane = threadIdx.x & 31;
    const float* xr = x + (size_t)row * DD;
    const float* w2 = wg + DD;
    float s = 0.f;
    #pragma unroll 4
    for (int d = lane; d < DD; d += 32) s = fmaf(xr[d], w2[d], s);
    #pragma unroll
    for (int off = 16; off > 0; off >>= 1)
        s += __shfl_xor_sync(0xffffffffu, s, off);
    s *= LOG2E;
    if (lane == 0) { g_c[row] = s; cmax[warp] = s; }
    __syncthreads();
    if (threadIdx.x == 0) {
        float m = cmax[0];
        #pragma unroll
        for (int i = 1; i < 8; ++i) m = fmaxf(m, cmax[i]);
        atomicMax(&g_maxc_bits[row >> 11], enc_ord(m));
    }
}

// ---------------------------------------------------------------------------
// Kernel 3: flash attention, bf16 mma, triple-buffered cp.async, P in
// registers, static per-row exponent bound. Fused per-16-key chunk with a
// one-chunk adjacency register prefetch: chunk ch+1's adj loads are issued
// while chunk ch's S-mma is in flight, hiding the scattered-LDG latency.
// CTA = (64-query tile, h, b), 128 threads = 4 warps x 16 rows.
// ---------------------------------------------------------------------------
__global__ __launch_bounds__(128, 4)
void attn_kernel(const float* __restrict__ x, const float* __restrict__ adj,
                 float* __restrict__ out)
{
    extern __shared__ __nv_bfloat16 asm_buf[];
    const int TB = 64 * 72;
    __nv_bfloat16* Kb0 = asm_buf;            // K buffers 0..2
    __nv_bfloat16* Vb0 = asm_buf + 3 * TB;   // V buffers 0..2

    int tid  = threadIdx.x;
    int warp = tid >> 5, lane = tid & 31;
    int g = lane >> 2, t4 = lane & 3;
    int qr = warp * 16;
    int i0 = blockIdx.x * 64;
    int h  = blockIdx.y;
    int b  = blockIdx.z;

    int a_r = ((lane >> 3) & 1) * 8 + (lane & 7);   // A non-trans (Q)
    int a_c = (lane >> 4) * 8;
    int k_r = (lane >> 4) * 8 + (lane & 7);         // B non-trans (K)
    int k_c = ((lane >> 3) & 1) * 8;
    int v_r = (lane & 7) + ((lane >> 3) & 1) * 8;   // B trans (V)
    int v_s = lane >> 4;

    const __nv_bfloat16* Qg = g_QKV[0] + (size_t)b * NN * DD + h * HD;
    const __nv_bfloat16* Kg = g_QKV[1] + (size_t)b * NN * DD + h * HD;
    const __nv_bfloat16* Vg = g_QKV[2] + (size_t)b * NN * DD + h * HD;
    const float* cv   = g_c + b * NN;
    const float* adjb = adj + (size_t)b * NN * NN;

    int srw[4], sce[4];
    #pragma unroll
    for (int it = 0; it < 4; ++it) {
        int c = tid + it * 128;
        srw[it] = c >> 3; sce[it] = (c & 7) * 8;
    }

    auto stage_kv = [&](int jt, int buf) {
        int j0 = jt * 64;
        #pragma unroll
        for (int it = 0; it < 4; ++it) {
            cpa16(Kb0 + buf * TB + srw[it] * 72 + sce[it],
                  Kg + (size_t)(j0 + srw[it]) * DD + sce[it]);
            cpa16(Vb0 + buf * TB + srw[it] * 72 + sce[it],
                  Vg + (size_t)(j0 + srw[it]) * DD + sce[it]);
        }
    };

    // ---- Stage Q into V buffer 2 (free until iter 1's staging) ----
    __nv_bfloat16* Qs = Vb0 + 2 * TB;
    #pragma unroll
    for (int it = 0; it < 4; ++it) {
        uint4 v = *(const uint4*)(Qg + (size_t)(i0 + srw[it]) * DD + sce[it]);
        *(uint4*)&Qs[srw[it] * 72 + sce[it]] = v;
    }
    stage_kv(0, 0); CP_COMMIT;
    __syncthreads();

    uint32_t qa[4][4];
    #pragma unroll
    for (int ch = 0; ch < 4; ++ch)
        ldm_x4(qa[ch], &Qs[(qr + a_r) * 72 + ch * 16 + a_c]);
    // iter-0's block barrier protects Qs before iter-1 stages buffer 2.

    // ---- per-row ||q|| from fragments (rows live in 4-lane groups) ----
    float nq0 = 0.f, nq1 = 0.f;
    #pragma unroll
    for (int ch = 0; ch < 4; ++ch) {
        float2 f;
        f = __bfloat1622float2(*(__nv_bfloat162*)&qa[ch][0]);
        nq0 = fmaf(f.x, f.x, fmaf(f.y, f.y, nq0));
        f = __bfloat1622float2(*(__nv_bfloat162*)&qa[ch][2]);
        nq0 = fmaf(f.x, f.x, fmaf(f.y, f.y, nq0));
        f = __bfloat1622float2(*(__nv_bfloat162*)&qa[ch][1]);
        nq1 = fmaf(f.x, f.x, fmaf(f.y, f.y, nq1));
        f = __bfloat1622float2(*(__nv_bfloat162*)&qa[ch][3]);
        nq1 = fmaf(f.x, f.x, fmaf(f.y, f.y, nq1));
    }
    nq0 += __shfl_xor_sync(0xffffffffu, nq0, 1);
    nq0 += __shfl_xor_sync(0xffffffffu, nq0, 2);
    nq1 += __shfl_xor_sync(0xffffffffu, nq1, 1);
    nq1 += __shfl_xor_sync(0xffffffffu, nq1, 2);

    float maxk = sqrtf(__uint_as_float(g_maxk_bits[b * HH + h]));
    float maxc = dec_ord(g_maxc_bits[b]);
    float m0 = SCLOG * sqrtf(nq0) * maxk + maxc + 1.0f;
    float m1 = SCLOG * sqrtf(nq1) * maxk + maxc + 1.0f;

    int r0g = i0 + qr + g, r1g = r0g + 8;
    const float* adjr0 = adjb + (size_t)r0g * NN + 2 * t4;
    const float* adjr1 = adjb + (size_t)r1g * NN + 2 * t4;
    float rs0 = 0.f, rs1 = 0.f;   // per-thread l partials across ALL iterations
    float o[8][4] = {};

    for (int jt = 0; jt < NN / 64; ++jt) {
        int j0 = jt * 64;
        int buf = jt % 3;
        if (jt + 1 < NN / 64) { stage_kv(jt + 1, (jt + 1) % 3); CP_COMMIT; CP_WAIT1; }
        else                  { CP_WAIT0; }
        __syncthreads();

        const __nv_bfloat16* Kt = Kb0 + buf * TB;
        const __nv_bfloat16* Vt = Vb0 + buf * TB;

        // prefetch adjacency for chunk 0
        float2 ad0[2], ad1[2];
        #pragma unroll
        for (int w = 0; w < 2; ++w) {
            ad0[w] = *(const float2*)(adjr0 + j0 + w * 8);
            ad1[w] = *(const float2*)(adjr1 + j0 + w * 8);
        }

        // ---- fused per-16-key chunk: S -> p/pack -> PV, adj prefetched ----
        #pragma unroll
        for (int ch = 0; ch < 4; ++ch) {
            // S for key chunk ch (n-tiles 2ch, 2ch+1), contraction over k
            float s2[2][4] = {};
            #pragma unroll
            for (int kch = 0; kch < 4; ++kch) {
                uint32_t kb[4];
                ldm_x4(kb, &Kt[(ch * 16 + k_r) * 72 + kch * 16 + k_c]);
                mma16(s2[0], qa[kch], kb[0], kb[1], s2[0]);
                mma16(s2[1], qa[kch], kb[2], kb[3], s2[1]);
            }

            // issue next chunk's adjacency loads while S is still settling
            float2 nad0[2], nad1[2];
            if (ch < 3) {
                #pragma unroll
                for (int w = 0; w < 2; ++w) {
                    nad0[w] = *(const float2*)(adjr0 + j0 + (ch + 1) * 16 + w * 8);
                    nad1[w] = *(const float2*)(adjr1 + j0 + (ch + 1) * 16 + w * 8);
                }
            }

            // p = (adj+eps) * 2^(s*SC + c - m), packed into PV A-fragment
            uint32_t pac[4];
            #pragma unroll
            for (int w = 0; w < 2; ++w) {
                int jc = j0 + ch * 16 + w * 8 + 2 * t4;
                float2 cc = *(const float2*)(cv + jc);
                float c0x = cc.x - m0, c0y = cc.y - m0;
                float c1x = cc.x - m1, c1y = cc.y - m1;
                float p00 = ex2f(fmaf(s2[w][0], SCLOG, c0x)) * (ad0[w].x + 1e-9f);
                float p01 = ex2f(fmaf(s2[w][1], SCLOG, c0y)) * (ad0[w].y + 1e-9f);
                float p10 = ex2f(fmaf(s2[w][2], SCLOG, c1x)) * (ad1[w].x + 1e-9f);
                float p11 = ex2f(fmaf(s2[w][3], SCLOG, c1y)) * (ad1[w].y + 1e-9f);
                rs0 += p00 + p01; rs1 += p10 + p11;
                pac[2 * w]     = pack_bf16(p00, p01);
                pac[2 * w + 1] = pack_bf16(p10, p11);
            }

            // PV for this key chunk
            #pragma unroll
            for (int np = 0; np < 4; ++np) {
                uint32_t vb[4];
                ldm_x4_trans(vb, &Vt[(ch * 16 + v_r) * 72 + (2 * np + v_s) * 8]);
                mma16(o[2 * np],     pac, vb[0], vb[1], o[2 * np]);
                mma16(o[2 * np + 1], pac, vb[2], vb[3], o[2 * np + 1]);
            }

            if (ch < 3) {
                #pragma unroll
                for (int w = 0; w < 2; ++w) { ad0[w] = nad0[w]; ad1[w] = nad1[w]; }
            }
        }
    }

    // ---- single end-of-kernel l reduction ----
    rs0 += __shfl_xor_sync(0xffffffffu, rs0, 1);
    rs0 += __shfl_xor_sync(0xffffffffu, rs0, 2);
    rs1 += __shfl_xor_sync(0xffffffffu, rs1, 1);
    rs1 += __shfl_xor_sync(0xffffffffu, rs1, 2);

    // ---- epilogue: normalize + residual (fp32) ----
    float inv0 = __fdividef(1.0f, rs0);
    float inv1 = __fdividef(1.0f, rs1);
    #pragma unroll
    for (int n = 0; n < 8; ++n) {
        int col = h * HD + n * 8 + 2 * t4;
        float2 x0 = *(const float2*)(x + ((size_t)b * NN + r0g) * DD + col);
        float2 x1 = *(const float2*)(x + ((size_t)b * NN + r1g) * DD + col);
        float2 o0 = {fmaf(o[n][0], inv0, x0.x), fmaf(o[n][1], inv0, x0.y)};
        float2 o1 = {fmaf(o[n][2], inv1, x1.x), fmaf(o[n][3], inv1, x1.y)};
        *(float2*)(out + ((size_t)b * NN + r0g) * DD + col) = o0;
        *(float2*)(out + ((size_t)b * NN + r1g) * DD + col) = o1;
    }
}

// ---------------------------------------------------------------------------
extern "C" void kernel_launch(void* const* d_in, const int* in_sizes, int n_in,
                              void* d_out, int out_size)
{
    const float* x   = (const float*)d_in[0];
    const float* adj = (const float*)d_in[1];
    const float* Wq  = (const float*)d_in[2];
    const float* bq  = (const float*)d_in[3];
    const float* Wk  = (const float*)d_in[4];
    const float* bk  = (const float*)d_in[5];
    const float* Wv  = (const float*)d_in[6];
    const float* bv  = (const float*)d_in[7];
    const float* wg  = (const float*)d_in[8];
    // d_in[9] (b_g) cancels inside the softmax; unused.
    float* out = (float*)d_out;

    const int qkv_smem = (2 * 128 * 72 + 2 * 64 * 72) * 2;   // 55296 B
    cudaFuncSetAttribute((const void*)qkv_gemm,
                         cudaFuncAttributeMaxDynamicSharedMemorySize, qkv_smem);
    const int attn_smem = 6 * 64 * 72 * 2;                   // 55296 B
    cudaFuncSetAttribute((const void*)attn_kernel,
                         cudaFuncAttributeMaxDynamicSharedMemorySize, attn_smem);

    convert_kernel<<<1408, 256>>>(x, Wq, Wk, Wv);
    gate_kernel<<<ROWS / 8, 256>>>(x, wg);
    qkv_gemm<<<dim3(DD / 64, ROWS / 128, 3), 256, qkv_smem>>>(bq, bk, bv);
    attn_kernel<<<dim3(NN / 64, HH, BB), 128, attn_smem>>>(x, adj, out);
}

// round 14
// speedup vs baseline: 1.5460x; 1.1188x over previous
#include <cuda_runtime.h>
#include <cuda_bf16.h>
#include <cstdint>

#define BB 2
#define NN 2048
#define DD 512
#define HH 8
#define HD 64
#define ROWS (BB*NN)

// Scratch (no allocations allowed)
__device__ __nv_bfloat16 g_QKV[3][(size_t)ROWS * DD];   // Q,K,V projections
__device__ __nv_bfloat16 g_Xb[(size_t)ROWS * DD];       // x in bf16
__device__ __nv_bfloat16 g_Wb[3][(size_t)DD * DD];      // W_q/k/v in bf16
__device__ float g_c[ROWS];                             // gate vec (log2-scaled)
__device__ unsigned g_maxk_bits[BB * HH];               // max_j ||k_j||^2 (float bits)
__device__ unsigned g_maxc_bits[BB];                    // max_j c_j (monotone-encoded)

#define LOG2E 1.4426950408889634f
#define SCLOG (0.125f * LOG2E)

// ---------------------------------------------------------------------------
// helpers
// ---------------------------------------------------------------------------
__device__ __forceinline__ float ex2f(float x) {        // 2^x on MUFU
    float r;
    asm("ex2.approx.f32 %0, %1;" : "=f"(r) : "f"(x));
    return r;
}
__device__ __forceinline__ uint32_t pack_bf16(float lo, float hi) {
    uint32_t r;
    asm("cvt.rn.bf16x2.f32 %0, %1, %2;" : "=r"(r) : "f"(hi), "f"(lo));
    return r;
}
__device__ __forceinline__ unsigned enc_ord(float f) {  // monotone float->uint
    int i = __float_as_int(f);
    return (i < 0) ? ~(unsigned)i : ((unsigned)i | 0x80000000u);
}
__device__ __forceinline__ float dec_ord(unsigned u) {
    int i = (u & 0x80000000u) ? (int)(u & 0x7fffffffu) : (int)~u;
    return __int_as_float(i);
}
// key permutation: fragment row f -> physical key offset within 64-tile.
// f = 16ch + 8w + 2t4 + e  ->  p = 16ch + 4t4 + 2w + e
__device__ __host__ __forceinline__ int prow(int r) {
    return (r & 0x30) | (((r >> 1) & 3) << 2) | (((r >> 3) & 1) << 1) | (r & 1);
}
__device__ __forceinline__ void mma16(float* d, const uint32_t* a,
                                      uint32_t b0, uint32_t b1, const float* c) {
    asm("mma.sync.aligned.m16n8k16.row.col.f32.bf16.bf16.f32 "
        "{%0,%1,%2,%3}, {%4,%5,%6,%7}, {%8,%9}, {%10,%11,%12,%13};"
        : "=f"(d[0]), "=f"(d[1]), "=f"(d[2]), "=f"(d[3])
        : "r"(a[0]), "r"(a[1]), "r"(a[2]), "r"(a[3]),
          "r"(b0), "r"(b1),
          "f"(c[0]), "f"(c[1]), "f"(c[2]), "f"(c[3]));
}
__device__ __forceinline__ void ldm_x4(uint32_t* r, const void* ptr) {
    uint32_t a = (uint32_t)__cvta_generic_to_shared(ptr);
    asm volatile("ldmatrix.sync.aligned.m8n8.x4.shared.b16 "
                 "{%0,%1,%2,%3}, [%4];"
                 : "=r"(r[0]), "=r"(r[1]), "=r"(r[2]), "=r"(r[3]) : "r"(a));
}
__device__ __forceinline__ void ldm_x4_trans(uint32_t* r, const void* ptr) {
    uint32_t a = (uint32_t)__cvta_generic_to_shared(ptr);
    asm volatile("ldmatrix.sync.aligned.m8n8.x4.trans.shared.b16 "
                 "{%0,%1,%2,%3}, [%4];"
                 : "=r"(r[0]), "=r"(r[1]), "=r"(r[2]), "=r"(r[3]) : "r"(a));
}
__device__ __forceinline__ void cpa16(void* smem_dst, const void* gsrc) {
    uint32_t d = (uint32_t)__cvta_generic_to_shared(smem_dst);
    asm volatile("cp.async.cg.shared.global [%0], [%1], 16;" :: "r"(d), "l"(gsrc));
}
#define CP_COMMIT asm volatile("cp.async.commit_group;" ::: "memory")
#define CP_WAIT1  asm volatile("cp.async.wait_group 1;" ::: "memory")
#define CP_WAIT0  asm volatile("cp.async.wait_group 0;" ::: "memory")

// ---------------------------------------------------------------------------
// Kernel 0: fp32 -> bf16 conversion of W_q/k/v only (x handled by gate).
// Block 0 also resets the bound atomics.
// ---------------------------------------------------------------------------
__global__ __launch_bounds__(256)
void convert_kernel(const float* __restrict__ Wq, const float* __restrict__ Wk,
                    const float* __restrict__ Wv)
{
    if (blockIdx.x == 0) {
        int t = threadIdx.x;
        if (t < BB * HH) g_maxk_bits[t] = 0u;             // ||k||^2 >= 0
        if (t < BB)      g_maxc_bits[t] = 0u;             // encodes very-negative
    }
    int idx = blockIdx.x * 256 + threadIdx.x;             // 98304 threads
    int z = idx >> 15;                                    // 32768 chunks per W
    int o = idx & 32767;
    const float* src = (z == 0) ? Wq : (z == 1) ? Wk : Wv;
    __nv_bfloat16* dst = g_Wb[z];
    size_t off = (size_t)o * 8;
    float4 v0 = *(const float4*)(src + off);
    float4 v1 = *(const float4*)(src + off + 4);
    uint4 u;
    u.x = pack_bf16(v0.x, v0.y);
    u.y = pack_bf16(v0.z, v0.w);
    u.z = pack_bf16(v1.x, v1.y);
    u.w = pack_bf16(v1.z, v1.w);
    *(uint4*)(dst + off) = u;
}

// ---------------------------------------------------------------------------
// Kernel 2 (runs before qkv): per-row gate dot c = (x . w_g[D:]) * log2e,
// per-batch max-c fold, AND x -> bf16 conversion (x is read here anyway).
// One warp per row, 8 rows per block.
// ---------------------------------------------------------------------------
__global__ __launch_bounds__(256)
void gate_kernel(const float* __restrict__ x, const float* __restrict__ wg)
{
    __shared__ float cmax[8];
    int row  = blockIdx.x * 8 + (threadIdx.x >> 5);
    int warp = threadIdx.x >> 5;
    int lane = threadIdx.x & 31;
    const float* xr = x + (size_t)row * DD;
    const float* w2 = wg + DD;
    __nv_bfloat16* xb = g_Xb + (size_t)row * DD;
    float s = 0.f;
    #pragma unroll
    for (int i = 0; i < 4; ++i) {
        int d = i * 128 + lane * 4;
        float4 v = *(const float4*)(xr + d);
        float4 w4 = *(const float4*)(w2 + d);
        s = fmaf(v.x, w4.x, fmaf(v.y, w4.y, fmaf(v.z, w4.z, fmaf(v.w, w4.w, s))));
        uint2 u = {pack_bf16(v.x, v.y), pack_bf16(v.z, v.w)};
        *(uint2*)(xb + d) = u;
    }
    #pragma unroll
    for (int off = 16; off > 0; off >>= 1)
        s += __shfl_xor_sync(0xffffffffu, s, off);
    s *= LOG2E;
    if (lane == 0) { g_c[row] = s; cmax[warp] = s; }
    __syncthreads();
    if (threadIdx.x == 0) {
        float m = cmax[0];
        #pragma unroll
        for (int i = 1; i < 8; ++i) m = fmaxf(m, cmax[i]);
        atomicMax(&g_maxc_bits[row >> 11], enc_ord(m));
    }
}

// ---------------------------------------------------------------------------
// Kernel 1: fused QKV projection, pure bf16, cp.async double-buffered, BK=64.
// z==1 (K) CTAs fold the per-(b,h) max ||k||^2 bound in the epilogue.
// ---------------------------------------------------------------------------
__global__ __launch_bounds__(256)
void qkv_gemm(const float* __restrict__ bq, const float* __restrict__ bk,
              const float* __restrict__ bv)
{
    extern __shared__ __nv_bfloat16 dsm[];
    __nv_bfloat16* Xs[2] = {dsm, dsm + 128 * 72};
    __nv_bfloat16* Ws[2] = {dsm + 2 * 128 * 72, dsm + 2 * 128 * 72 + 64 * 72};

    int z = blockIdx.z;
    const __nv_bfloat16* Xg = g_Xb;
    const __nv_bfloat16* Wg = g_Wb[z];
    const float* bias = (z == 0) ? bq : (z == 1) ? bk : bv;
    __nv_bfloat16* C = g_QKV[z];

    int row0 = blockIdx.y * 128;
    int col0 = blockIdx.x * 64;
    int tid  = threadIdx.x;
    int warp = tid >> 5, lane = tid & 31;
    int g = lane >> 2, t4 = lane & 3;
    int wm = (warp & 3) * 32;
    int wn = (warp >> 2) * 32;

    int a_r = ((lane >> 3) & 1) * 8 + (lane & 7);
    int a_c = (lane >> 4) * 8;
    int v_r = (lane & 7) + ((lane >> 3) & 1) * 8;
    int v_s = lane >> 4;

    int xrw[4], xce[4];
    #pragma unroll
    for (int it = 0; it < 4; ++it) {
        int c = tid + it * 256;
        xrw[it] = c >> 3; xce[it] = (c & 7) * 8;
    }
    int wrw[2], wce[2];
    #pragma unroll
    for (int it = 0; it < 2; ++it) {
        int c = tid + it * 256;
        wrw[it] = c >> 3; wce[it] = (c & 7) * 8;
    }

    auto stage = [&](int kit, int buf) {
        int k0 = kit * 64;
        #pragma unroll
        for (int it = 0; it < 4; ++it)
            cpa16(&Xs[buf][xrw[it] * 72 + xce[it]],
                  Xg + (size_t)(row0 + xrw[it]) * DD + k0 + xce[it]);
        #pragma unroll
        for (int it = 0; it < 2; ++it)
            cpa16(&Ws[buf][wrw[it] * 72 + wce[it]],
                  Wg + (size_t)(k0 + wrw[it]) * DD + col0 + wce[it]);
    };

    float acc[2][4][4] = {};

    stage(0, 0); CP_COMMIT;

    for (int it = 0; it < 8; ++it) {
        int buf = it & 1;
        if (it < 7) { stage(it + 1, buf ^ 1); CP_COMMIT; CP_WAIT1; }
        else        { CP_WAIT0; }
        __syncthreads();

        #pragma unroll
        for (int ch = 0; ch < 4; ++ch) {
            int kk = ch * 16;
            uint32_t a[2][4];
            ldm_x4(a[0], &Xs[buf][(wm + a_r) * 72 + kk + a_c]);
            ldm_x4(a[1], &Xs[buf][(wm + 16 + a_r) * 72 + kk + a_c]);
            uint32_t b0[4], b1[4];
            ldm_x4_trans(b0, &Ws[buf][(kk + v_r) * 72 + wn + v_s * 8]);
            ldm_x4_trans(b1, &Ws[buf][(kk + v_r) * 72 + wn + 16 + v_s * 8]);
            #pragma unroll
            for (int m = 0; m < 2; ++m) {
                mma16(acc[m][0], a[m], b0[0], b0[1], acc[m][0]);
                mma16(acc[m][1], a[m], b0[2], b0[3], acc[m][1]);
                mma16(acc[m][2], a[m], b1[0], b1[1], acc[m][2]);
                mma16(acc[m][3], a[m], b1[2], b1[3], acc[m][3]);
            }
        }
        __syncthreads();
    }

    // epilogue: + bias (in-place), pack to bf16, store
    #pragma unroll
    for (int n = 0; n < 4; ++n) {
        int col = col0 + wn + n * 8 + 2 * t4;
        float2 bb = *(const float2*)(bias + col);
        #pragma unroll
        for (int m = 0; m < 2; ++m) {
            int r0 = row0 + wm + m * 16 + g;
            acc[m][n][0] += bb.x; acc[m][n][1] += bb.y;
            acc[m][n][2] += bb.x; acc[m][n][3] += bb.y;
            *(uint32_t*)(C + (size_t)r0 * DD + col) =
                pack_bf16(acc[m][n][0], acc[m][n][1]);
            *(uint32_t*)(C + (size_t)(r0 + 8) * DD + col) =
                pack_bf16(acc[m][n][2], acc[m][n][3]);
        }
    }

    // ---- K-norm bound fold (z==1 only) ----
    if (z == 1) {
        float* rn = (float*)dsm;          // reuse smem (post-barrier above)
        if (tid < 128) rn[tid] = 0.f;
        __syncthreads();
        #pragma unroll
        for (int m = 0; m < 2; ++m) {
            float s0 = 0.f, s1 = 0.f;
            #pragma unroll
            for (int n = 0; n < 4; ++n) {
                s0 = fmaf(acc[m][n][0], acc[m][n][0],
                     fmaf(acc[m][n][1], acc[m][n][1], s0));
                s1 = fmaf(acc[m][n][2], acc[m][n][2],
                     fmaf(acc[m][n][3], acc[m][n][3], s1));
            }
            s0 += __shfl_xor_sync(0xffffffffu, s0, 1);
            s0 += __shfl_xor_sync(0xffffffffu, s0, 2);
            s1 += __shfl_xor_sync(0xffffffffu, s1, 1);
            s1 += __shfl_xor_sync(0xffffffffu, s1, 2);
            if (t4 == 0) {
                atomicAdd(&rn[wm + m * 16 + g], s0);
                atomicAdd(&rn[wm + m * 16 + 8 + g], s1);
            }
        }
        __syncthreads();
        if (tid < 128) {
            float v = rn[tid];
            #pragma unroll
            for (int off = 16; off > 0; off >>= 1)
                v = fmaxf(v, __shfl_xor_sync(0xffffffffu, v, off));
            if ((tid & 31) == 0) {
                int bh = (row0 >= NN ? HH : 0) + (col0 >> 6);
                atomicMax(&g_maxk_bits[bh], __float_as_uint(v));
            }
        }
    }
}

// ---------------------------------------------------------------------------
// Kernel 3: flash attention, bf16 mma, triple-buffered cp.async, P in
// registers, static per-row exponent bound. KEYS ARE PERMUTED within each
// 64-tile (fragment row f <-> physical key prow(f)) so each thread's
// adjacency + gate values per chunk are ONE contiguous float4: adjacency
// LDG instructions and L1 wavefronts halve. Softmax is key-order-invariant,
// so the result is exact. CTA = (64-query tile, h, b), 4 warps x 16 rows.
// ---------------------------------------------------------------------------
__global__ __launch_bounds__(128, 4)
void attn_kernel(const float* __restrict__ x, const float* __restrict__ adj,
                 float* __restrict__ out)
{
    extern __shared__ __nv_bfloat16 asm_buf[];
    const int TB = 64 * 72;
    __nv_bfloat16* Kb0 = asm_buf;            // K buffers 0..2
    __nv_bfloat16* Vb0 = asm_buf + 3 * TB;   // V buffers 0..2

    int tid  = threadIdx.x;
    int warp = tid >> 5, lane = tid & 31;
    int g = lane >> 2, t4 = lane & 3;
    int qr = warp * 16;
    int i0 = blockIdx.x * 64;
    int h  = blockIdx.y;
    int b  = blockIdx.z;

    int a_r = ((lane >> 3) & 1) * 8 + (lane & 7);   // A non-trans (Q)
    int a_c = (lane >> 4) * 8;
    int k_r = (lane >> 4) * 8 + (lane & 7);         // B non-trans (K)
    int k_c = ((lane >> 3) & 1) * 8;
    int v_r = (lane & 7) + ((lane >> 3) & 1) * 8;   // B trans (V)
    int v_s = lane >> 4;

    const __nv_bfloat16* Qg = g_QKV[0] + (size_t)b * NN * DD + h * HD;
    const __nv_bfloat16* Kg = g_QKV[1] + (size_t)b * NN * DD + h * HD;
    const __nv_bfloat16* Vg = g_QKV[2] + (size_t)b * NN * DD + h * HD;
    const float* cv   = g_c + b * NN;
    const float* adjb = adj + (size_t)b * NN * NN;

    int srw[4], sce[4], psw[4];
    #pragma unroll
    for (int it = 0; it < 4; ++it) {
        int c = tid + it * 128;
        srw[it] = c >> 3; sce[it] = (c & 7) * 8;
        psw[it] = prow(srw[it]);                    // permuted gmem key row
    }

    auto stage_kv = [&](int jt, int buf) {
        int j0 = jt * 64;
        #pragma unroll
        for (int it = 0; it < 4; ++it) {
            cpa16(Kb0 + buf * TB + srw[it] * 72 + sce[it],
                  Kg + (size_t)(j0 + psw[it]) * DD + sce[it]);
            cpa16(Vb0 + buf * TB + srw[it] * 72 + sce[it],
                  Vg + (size_t)(j0 + psw[it]) * DD + sce[it]);
        }
    };

    // ---- Stage Q into V buffer 2 (free until iter 1's staging) ----
    __nv_bfloat16* Qs = Vb0 + 2 * TB;
    #pragma unroll
    for (int it = 0; it < 4; ++it) {
        uint4 v = *(const uint4*)(Qg + (size_t)(i0 + srw[it]) * DD + sce[it]);
        *(uint4*)&Qs[srw[it] * 72 + sce[it]] = v;
    }
    stage_kv(0, 0); CP_COMMIT;
    __syncthreads();

    uint32_t qa[4][4];
    #pragma unroll
    for (int ch = 0; ch < 4; ++ch)
        ldm_x4(qa[ch], &Qs[(qr + a_r) * 72 + ch * 16 + a_c]);
    // iter-0's block barrier protects Qs before iter-1 stages buffer 2.

    // ---- per-row ||q|| from fragments (rows live in 4-lane groups) ----
    float nq0 = 0.f, nq1 = 0.f;
    #pragma unroll
    for (int ch = 0; ch < 4; ++ch) {
        float2 f;
        f = __bfloat1622float2(*(__nv_bfloat162*)&qa[ch][0]);
        nq0 = fmaf(f.x, f.x, fmaf(f.y, f.y, nq0));
        f = __bfloat1622float2(*(__nv_bfloat162*)&qa[ch][2]);
        nq0 = fmaf(f.x, f.x, fmaf(f.y, f.y, nq0));
        f = __bfloat1622float2(*(__nv_bfloat162*)&qa[ch][1]);
        nq1 = fmaf(f.x, f.x, fmaf(f.y, f.y, nq1));
        f = __bfloat1622float2(*(__nv_bfloat162*)&qa[ch][3]);
        nq1 = fmaf(f.x, f.x, fmaf(f.y, f.y, nq1));
    }
    nq0 += __shfl_xor_sync(0xffffffffu, nq0, 1);
    nq0 += __shfl_xor_sync(0xffffffffu, nq0, 2);
    nq1 += __shfl_xor_sync(0xffffffffu, nq1, 1);
    nq1 += __shfl_xor_sync(0xffffffffu, nq1, 2);

    float maxk = sqrtf(__uint_as_float(g_maxk_bits[b * HH + h]));
    float maxc = dec_ord(g_maxc_bits[b]);
    float m0 = SCLOG * sqrtf(nq0) * maxk + maxc + 1.0f;
    float m1 = SCLOG * sqrtf(nq1) * maxk + maxc + 1.0f;

    int r0g = i0 + qr + g, r1g = r0g + 8;
    // contiguous-per-chunk bases (permuted key space): + 4*t4
    const float* adjr0 = adjb + (size_t)r0g * NN + 4 * t4;
    const float* adjr1 = adjb + (size_t)r1g * NN + 4 * t4;
    const float* cvq   = cv + 4 * t4;
    float rs0 = 0.f, rs1 = 0.f;
    float o[8][4] = {};

    for (int jt = 0; jt < NN / 64; ++jt) {
        int j0 = jt * 64;
        int buf = jt % 3;
        if (jt + 1 < NN / 64) { stage_kv(jt + 1, (jt + 1) % 3); CP_COMMIT; CP_WAIT1; }
        else                  { CP_WAIT0; }
        __syncthreads();

        const __nv_bfloat16* Kt = Kb0 + buf * TB;
        const __nv_bfloat16* Vt = Vb0 + buf * TB;

        // prefetch adjacency for chunk 0 (one float4 per row)
        float4 aq0 = *(const float4*)(adjr0 + j0);
        float4 aq1 = *(const float4*)(adjr1 + j0);

        // ---- fused per-16-key chunk: S -> p/pack -> PV ----
        #pragma unroll
        for (int ch = 0; ch < 4; ++ch) {
            float s2[2][4] = {};
            #pragma unroll
            for (int kch = 0; kch < 4; ++kch) {
                uint32_t kb[4];
                ldm_x4(kb, &Kt[(ch * 16 + k_r) * 72 + kch * 16 + k_c]);
                mma16(s2[0], qa[kch], kb[0], kb[1], s2[0]);
                mma16(s2[1], qa[kch], kb[2], kb[3], s2[1]);
            }

            // next chunk's adjacency while S settles
            float4 nq0v, nq1v;
            if (ch < 3) {
                nq0v = *(const float4*)(adjr0 + j0 + (ch + 1) * 16);
                nq1v = *(const float4*)(adjr1 + j0 + (ch + 1) * 16);
            }

            float4 cq = *(const float4*)(cvq + j0 + ch * 16);
            const float* cqa = (const float*)&cq;
            const float* a0a = (const float*)&aq0;
            const float* a1a = (const float*)&aq1;

            uint32_t pac[4];
            #pragma unroll
            for (int w = 0; w < 2; ++w) {
                float cA = cqa[2 * w], cB = cqa[2 * w + 1];
                float p00 = ex2f(fmaf(s2[w][0], SCLOG, cA - m0)) * (a0a[2 * w]     + 1e-9f);
                float p01 = ex2f(fmaf(s2[w][1], SCLOG, cB - m0)) * (a0a[2 * w + 1] + 1e-9f);
                float p10 = ex2f(fmaf(s2[w][2], SCLOG, cA - m1)) * (a1a[2 * w]     + 1e-9f);
                float p11 = ex2f(fmaf(s2[w][3], SCLOG, cB - m1)) * (a1a[2 * w + 1] + 1e-9f);
                rs0 += p00 + p01; rs1 += p10 + p11;
                pac[2 * w]     = pack_bf16(p00, p01);
                pac[2 * w + 1] = pack_bf16(p10, p11);
            }

            #pragma unroll
            for (int np = 0; np < 4; ++np) {
                uint32_t vb[4];
                ldm_x4_trans(vb, &Vt[(ch * 16 + v_r) * 72 + (2 * np + v_s) * 8]);
                mma16(o[2 * np],     pac, vb[0], vb[1], o[2 * np]);
                mma16(o[2 * np + 1], pac, vb[2], vb[3], o[2 * np + 1]);
            }

            if (ch < 3) { aq0 = nq0v; aq1 = nq1v; }
        }
    }

    // ---- single end-of-kernel l reduction ----
    rs0 += __shfl_xor_sync(0xffffffffu, rs0, 1);
    rs0 += __shfl_xor_sync(0xffffffffu, rs0, 2);
    rs1 += __shfl_xor_sync(0xffffffffu, rs1, 1);
    rs1 += __shfl_xor_sync(0xffffffffu, rs1, 2);

    // ---- epilogue: normalize + residual (fp32) ----
    float inv0 = __fdividef(1.0f, rs0);
    float inv1 = __fdividef(1.0f, rs1);
    #pragma unroll
    for (int n = 0; n < 8; ++n) {
        int col = h * HD + n * 8 + 2 * t4;
        float2 x0 = *(const float2*)(x + ((size_t)b * NN + r0g) * DD + col);
        float2 x1 = *(const float2*)(x + ((size_t)b * NN + r1g) * DD + col);
        float2 o0 = {fmaf(o[n][0], inv0, x0.x), fmaf(o[n][1], inv0, x0.y)};
        float2 o1 = {fmaf(o[n][2], inv1, x1.x), fmaf(o[n][3], inv1, x1.y)};
        *(float2*)(out + ((size_t)b * NN + r0g) * DD + col) = o0;
        *(float2*)(out + ((size_t)b * NN + r1g) * DD + col) = o1;
    }
}

// ---------------------------------------------------------------------------
extern "C" void kernel_launch(void* const* d_in, const int* in_sizes, int n_in,
                              void* d_out, int out_size)
{
    const float* x   = (const float*)d_in[0];
    const float* adj = (const float*)d_in[1];
    const float* Wq  = (const float*)d_in[2];
    const float* bq  = (const float*)d_in[3];
    const float* Wk  = (const float*)d_in[4];
    const float* bk  = (const float*)d_in[5];
    const float* Wv  = (const float*)d_in[6];
    const float* bv  = (const float*)d_in[7];
    const float* wg  = (const float*)d_in[8];
    // d_in[9] (b_g) cancels inside the softmax; unused.
    float* out = (float*)d_out;

    const int qkv_smem = (2 * 128 * 72 + 2 * 64 * 72) * 2;   // 55296 B
    cudaFuncSetAttribute((const void*)qkv_gemm,
                         cudaFuncAttributeMaxDynamicSharedMemorySize, qkv_smem);
    const int attn_smem = 6 * 64 * 72 * 2;                   // 55296 B
    cudaFuncSetAttribute((const void*)attn_kernel,
                         cudaFuncAttributeMaxDynamicSharedMemorySize, attn_smem);

    convert_kernel<<<384, 256>>>(Wq, Wk, Wv);
    gate_kernel<<<ROWS / 8, 256>>>(x, wg);
    qkv_gemm<<<dim3(DD / 64, ROWS / 128, 3), 256, qkv_smem>>>(bq, bk, bv);
    attn_kernel<<<dim3(NN / 64, HH, BB), 128, attn_smem>>>(x, adj, out);
}

// round 15
// speedup vs baseline: 1.6351x; 1.0577x over previous
#include <cuda_runtime.h>
#include <cuda_bf16.h>
#include <cstdint>

#define BB 2
#define NN 2048
#define DD 512
#define HH 8
#define HD 64
#define ROWS (BB*NN)

// Scratch (no allocations allowed)
__device__ __nv_bfloat16 g_QKV[3][(size_t)ROWS * DD];   // Q,K,V projections
__device__ __nv_bfloat16 g_Xb[(size_t)ROWS * DD];       // x in bf16
__device__ __nv_bfloat16 g_Wb[3][(size_t)DD * DD];      // W_q/k/v in bf16
__device__ float g_c[ROWS];                             // gate vec (log2-scaled)
// Bound atomics: zero-initialized at module load; atomicMax over FIXED inputs
// is idempotent across graph replays (same work & same result every launch),
// so no reset is needed (a same-launch reset would be a race).
__device__ unsigned g_maxk_bits[BB * HH];               // max_j ||k_j||^2 (float bits)
__device__ unsigned g_maxc_bits[BB];                    // max_j c_j (monotone-encoded)

#define LOG2E 1.4426950408889634f
#define SCLOG (0.125f * LOG2E)

// ---------------------------------------------------------------------------
// helpers
// ---------------------------------------------------------------------------
__device__ __forceinline__ float ex2f(float x) {        // 2^x on MUFU
    float r;
    asm("ex2.approx.f32 %0, %1;" : "=f"(r) : "f"(x));
    return r;
}
__device__ __forceinline__ uint32_t pack_bf16(float lo, float hi) {
    uint32_t r;
    asm("cvt.rn.bf16x2.f32 %0, %1, %2;" : "=r"(r) : "f"(hi), "f"(lo));
    return r;
}
__device__ __forceinline__ unsigned enc_ord(float f) {  // monotone float->uint
    int i = __float_as_int(f);
    return (i < 0) ? ~(unsigned)i : ((unsigned)i | 0x80000000u);
}
__device__ __forceinline__ float dec_ord(unsigned u) {
    int i = (u & 0x80000000u) ? (int)(u & 0x7fffffffu) : (int)~u;
    return __int_as_float(i);
}
// key permutation: fragment row f -> physical key offset within 64-tile.
// f = 16ch + 8w + 2t4 + e  ->  p = 16ch + 4t4 + 2w + e
__device__ __host__ __forceinline__ int prow(int r) {
    return (r & 0x30) | (((r >> 1) & 3) << 2) | (((r >> 3) & 1) << 1) | (r & 1);
}
__device__ __forceinline__ void mma16(float* d, const uint32_t* a,
                                      uint32_t b0, uint32_t b1, const float* c) {
    asm("mma.sync.aligned.m16n8k16.row.col.f32.bf16.bf16.f32 "
        "{%0,%1,%2,%3}, {%4,%5,%6,%7}, {%8,%9}, {%10,%11,%12,%13};"
        : "=f"(d[0]), "=f"(d[1]), "=f"(d[2]), "=f"(d[3])
        : "r"(a[0]), "r"(a[1]), "r"(a[2]), "r"(a[3]),
          "r"(b0), "r"(b1),
          "f"(c[0]), "f"(c[1]), "f"(c[2]), "f"(c[3]));
}
__device__ __forceinline__ void ldm_x4(uint32_t* r, const void* ptr) {
    uint32_t a = (uint32_t)__cvta_generic_to_shared(ptr);
    asm volatile("ldmatrix.sync.aligned.m8n8.x4.shared.b16 "
                 "{%0,%1,%2,%3}, [%4];"
                 : "=r"(r[0]), "=r"(r[1]), "=r"(r[2]), "=r"(r[3]) : "r"(a));
}
__device__ __forceinline__ void ldm_x4_trans(uint32_t* r, const void* ptr) {
    uint32_t a = (uint32_t)__cvta_generic_to_shared(ptr);
    asm volatile("ldmatrix.sync.aligned.m8n8.x4.trans.shared.b16 "
                 "{%0,%1,%2,%3}, [%4];"
                 : "=r"(r[0]), "=r"(r[1]), "=r"(r[2]), "=r"(r[3]) : "r"(a));
}
__device__ __forceinline__ void cpa16(void* smem_dst, const void* gsrc) {
    uint32_t d = (uint32_t)__cvta_generic_to_shared(smem_dst);
    asm volatile("cp.async.cg.shared.global [%0], [%1], 16;" :: "r"(d), "l"(gsrc));
}
#define CP_COMMIT asm volatile("cp.async.commit_group;" ::: "memory")
#define CP_WAIT1  asm volatile("cp.async.wait_group 1;" ::: "memory")
#define CP_WAIT0  asm volatile("cp.async.wait_group 0;" ::: "memory")

// ---------------------------------------------------------------------------
// Kernel P: merged prep. Blocks 0..511: gate dot c = (x . w_g[D:]) * log2e
// per row (one warp per row), per-batch max-c fold, and x -> bf16 (x is
// being read anyway). Blocks 512..895: W_q/k/v fp32 -> bf16.
// ---------------------------------------------------------------------------
__global__ __launch_bounds__(256)
void prep_kernel(const float* __restrict__ x, const float* __restrict__ wg,
                 const float* __restrict__ Wq, const float* __restrict__ Wk,
                 const float* __restrict__ Wv)
{
    if (blockIdx.x < 512) {
        __shared__ float cmax[8];
        int row  = blockIdx.x * 8 + (threadIdx.x >> 5);
        int warp = threadIdx.x >> 5;
        int lane = threadIdx.x & 31;
        const float* xr = x + (size_t)row * DD;
        const float* w2 = wg + DD;
        __nv_bfloat16* xb = g_Xb + (size_t)row * DD;
        float s = 0.f;
        #pragma unroll
        for (int i = 0; i < 4; ++i) {
            int d = i * 128 + lane * 4;
            float4 v = *(const float4*)(xr + d);
            float4 w4 = *(const float4*)(w2 + d);
            s = fmaf(v.x, w4.x, fmaf(v.y, w4.y, fmaf(v.z, w4.z, fmaf(v.w, w4.w, s))));
            uint2 u = {pack_bf16(v.x, v.y), pack_bf16(v.z, v.w)};
            *(uint2*)(xb + d) = u;
        }
        #pragma unroll
        for (int off = 16; off > 0; off >>= 1)
            s += __shfl_xor_sync(0xffffffffu, s, off);
        s *= LOG2E;
        if (lane == 0) { g_c[row] = s; cmax[warp] = s; }
        __syncthreads();
        if (threadIdx.x == 0) {
            float m = cmax[0];
            #pragma unroll
            for (int i = 1; i < 8; ++i) m = fmaxf(m, cmax[i]);
            atomicMax(&g_maxc_bits[row >> 11], enc_ord(m));
        }
    } else {
        int idx = (blockIdx.x - 512) * 256 + threadIdx.x;  // 98304 threads
        int z = idx >> 15;
        int o = idx & 32767;
        const float* src = (z == 0) ? Wq : (z == 1) ? Wk : Wv;
        __nv_bfloat16* dst = g_Wb[z];
        size_t off = (size_t)o * 8;
        float4 v0 = *(const float4*)(src + off);
        float4 v1 = *(const float4*)(src + off + 4);
        uint4 u;
        u.x = pack_bf16(v0.x, v0.y);
        u.y = pack_bf16(v0.z, v0.w);
        u.z = pack_bf16(v1.x, v1.y);
        u.w = pack_bf16(v1.z, v1.w);
        *(uint4*)(dst + off) = u;
    }
}

// ---------------------------------------------------------------------------
// Kernel 1: fused QKV projection, pure bf16, cp.async double-buffered,
// 128x128 output tile, BK=64. 8 warps in a 4x2 grid; each warp computes
// 32x64 (mainloop ratio 6 ldm : 16 mma). z==1 (K) CTAs fold the per-(b,h)
// max ||k||^2 bound in the epilogue — each warp's 64 cols lie in ONE head
// and its 32 rows are warp-private, so it's a pure shuffle reduce.
// ---------------------------------------------------------------------------
__global__ __launch_bounds__(256)
void qkv_gemm(const float* __restrict__ bq, const float* __restrict__ bk,
              const float* __restrict__ bv)
{
    extern __shared__ __nv_bfloat16 dsm[];
    __nv_bfloat16* Xs[2] = {dsm, dsm + 128 * 72};
    __nv_bfloat16* Ws[2] = {dsm + 2 * 128 * 72, dsm + 2 * 128 * 72 + 64 * 136};

    int z = blockIdx.z;
    const __nv_bfloat16* Xg = g_Xb;
    const __nv_bfloat16* Wg = g_Wb[z];
    const float* bias = (z == 0) ? bq : (z == 1) ? bk : bv;
    __nv_bfloat16* C = g_QKV[z];

    int row0 = blockIdx.y * 128;
    int col0 = blockIdx.x * 128;
    int tid  = threadIdx.x;
    int warp = tid >> 5, lane = tid & 31;
    int g = lane >> 2, t4 = lane & 3;
    int wm = (warp & 3) * 32;
    int wn = (warp >> 2) * 64;

    int a_r = ((lane >> 3) & 1) * 8 + (lane & 7);
    int a_c = (lane >> 4) * 8;
    int v_r = (lane & 7) + ((lane >> 3) & 1) * 8;
    int v_s = lane >> 4;

    // staging: X 128x64 (1024 chunks), W 64x128 (1024 chunks); 4 each/thread
    int xrw[4], xce[4], wrw[4], wce[4];
    #pragma unroll
    for (int it = 0; it < 4; ++it) {
        int c = tid + it * 256;
        xrw[it] = c >> 3;  xce[it] = (c & 7) * 8;
        wrw[it] = c >> 4;  wce[it] = (c & 15) * 8;
    }

    auto stage = [&](int kit, int buf) {
        int k0 = kit * 64;
        #pragma unroll
        for (int it = 0; it < 4; ++it) {
            cpa16(&Xs[buf][xrw[it] * 72 + xce[it]],
                  Xg + (size_t)(row0 + xrw[it]) * DD + k0 + xce[it]);
            cpa16(&Ws[buf][wrw[it] * 136 + wce[it]],
                  Wg + (size_t)(k0 + wrw[it]) * DD + col0 + wce[it]);
        }
    };

    float acc[2][8][4] = {};

    stage(0, 0); CP_COMMIT;

    for (int it = 0; it < 8; ++it) {
        int buf = it & 1;
        if (it < 7) { stage(it + 1, buf ^ 1); CP_COMMIT; CP_WAIT1; }
        else        { CP_WAIT0; }
        __syncthreads();

        #pragma unroll
        for (int ch = 0; ch < 4; ++ch) {
            int kk = ch * 16;
            uint32_t a[2][4];
            ldm_x4(a[0], &Xs[buf][(wm + a_r) * 72 + kk + a_c]);
            ldm_x4(a[1], &Xs[buf][(wm + 16 + a_r) * 72 + kk + a_c]);
            uint32_t bf[4][4];
            #pragma unroll
            for (int nb = 0; nb < 4; ++nb)
                ldm_x4_trans(bf[nb], &Ws[buf][(kk + v_r) * 136 + wn + nb * 16 + v_s * 8]);
            #pragma unroll
            for (int m = 0; m < 2; ++m)
                #pragma unroll
                for (int nb = 0; nb < 4; ++nb) {
                    mma16(acc[m][2 * nb],     a[m], bf[nb][0], bf[nb][1], acc[m][2 * nb]);
                    mma16(acc[m][2 * nb + 1], a[m], bf[nb][2], bf[nb][3], acc[m][2 * nb + 1]);
                }
        }
        __syncthreads();
    }

    // epilogue: + bias (in-place), pack to bf16, store
    #pragma unroll
    for (int n = 0; n < 8; ++n) {
        int col = col0 + wn + n * 8 + 2 * t4;
        float2 bb = *(const float2*)(bias + col);
        #pragma unroll
        for (int m = 0; m < 2; ++m) {
            int r0 = row0 + wm + m * 16 + g;
            acc[m][n][0] += bb.x; acc[m][n][1] += bb.y;
            acc[m][n][2] += bb.x; acc[m][n][3] += bb.y;
            *(uint32_t*)(C + (size_t)r0 * DD + col) =
                pack_bf16(acc[m][n][0], acc[m][n][1]);
            *(uint32_t*)(C + (size_t)(r0 + 8) * DD + col) =
                pack_bf16(acc[m][n][2], acc[m][n][3]);
        }
    }

    // ---- K-norm bound fold (z==1): warp-private rows, one head per warp ----
    if (z == 1) {
        float mx = 0.f;
        #pragma unroll
        for (int m = 0; m < 2; ++m) {
            float s0 = 0.f, s1 = 0.f;   // rows wm+m*16+g and +8 (this warp's 64 cols)
            #pragma unroll
            for (int n = 0; n < 8; ++n) {
                s0 = fmaf(acc[m][n][0], acc[m][n][0],
                     fmaf(acc[m][n][1], acc[m][n][1], s0));
                s1 = fmaf(acc[m][n][2], acc[m][n][2],
                     fmaf(acc[m][n][3], acc[m][n][3], s1));
            }
            s0 += __shfl_xor_sync(0xffffffffu, s0, 1);
            s0 += __shfl_xor_sync(0xffffffffu, s0, 2);
            s1 += __shfl_xor_sync(0xffffffffu, s1, 1);
            s1 += __shfl_xor_sync(0xffffffffu, s1, 2);
            mx = fmaxf(mx, fmaxf(s0, s1));
        }
        #pragma unroll
        for (int off = 16; off >= 4; off >>= 1)
            mx = fmaxf(mx, __shfl_xor_sync(0xffffffffu, mx, off));
        if (lane == 0) {
            int bh = (row0 >= NN ? HH : 0) + ((col0 + wn) >> 6);
            atomicMax(&g_maxk_bits[bh], __float_as_uint(mx));
        }
    }
}

// ---------------------------------------------------------------------------
// Kernel 3: flash attention, bf16 mma, triple-buffered cp.async, P in
// registers, static per-row exponent bound. Keys permuted within each
// 64-tile (fragment row f <-> physical key prow(f)) so each thread's
// adjacency + gate values per chunk are ONE contiguous float4. Softmax is
// key-order-invariant, so the result is exact.
// CTA = (64-query tile, h, b), 4 warps x 16 rows.  [unchanged from R14]
// ---------------------------------------------------------------------------
__global__ __launch_bounds__(128, 4)
void attn_kernel(const float* __restrict__ x, const float* __restrict__ adj,
                 float* __restrict__ out)
{
    extern __shared__ __nv_bfloat16 asm_buf[];
    const int TB = 64 * 72;
    __nv_bfloat16* Kb0 = asm_buf;            // K buffers 0..2
    __nv_bfloat16* Vb0 = asm_buf + 3 * TB;   // V buffers 0..2

    int tid  = threadIdx.x;
    int warp = tid >> 5, lane = tid & 31;
    int g = lane >> 2, t4 = lane & 3;
    int qr = warp * 16;
    int i0 = blockIdx.x * 64;
    int h  = blockIdx.y;
    int b  = blockIdx.z;

    int a_r = ((lane >> 3) & 1) * 8 + (lane & 7);   // A non-trans (Q)
    int a_c = (lane >> 4) * 8;
    int k_r = (lane >> 4) * 8 + (lane & 7);         // B non-trans (K)
    int k_c = ((lane >> 3) & 1) * 8;
    int v_r = (lane & 7) + ((lane >> 3) & 1) * 8;   // B trans (V)
    int v_s = lane >> 4;

    const __nv_bfloat16* Qg = g_QKV[0] + (size_t)b * NN * DD + h * HD;
    const __nv_bfloat16* Kg = g_QKV[1] + (size_t)b * NN * DD + h * HD;
    const __nv_bfloat16* Vg = g_QKV[2] + (size_t)b * NN * DD + h * HD;
    const float* cv   = g_c + b * NN;
    const float* adjb = adj + (size_t)b * NN * NN;

    int srw[4], sce[4], psw[4];
    #pragma unroll
    for (int it = 0; it < 4; ++it) {
        int c = tid + it * 128;
        srw[it] = c >> 3; sce[it] = (c & 7) * 8;
        psw[it] = prow(srw[it]);                    // permuted gmem key row
    }

    auto stage_kv = [&](int jt, int buf) {
        int j0 = jt * 64;
        #pragma unroll
        for (int it = 0; it < 4; ++it) {
            cpa16(Kb0 + buf * TB + srw[it] * 72 + sce[it],
                  Kg + (size_t)(j0 + psw[it]) * DD + sce[it]);
            cpa16(Vb0 + buf * TB + srw[it] * 72 + sce[it],
                  Vg + (size_t)(j0 + psw[it]) * DD + sce[it]);
        }
    };

    // ---- Stage Q into V buffer 2 (free until iter 1's staging) ----
    __nv_bfloat16* Qs = Vb0 + 2 * TB;
    #pragma unroll
    for (int it = 0; it < 4; ++it) {
        uint4 v = *(const uint4*)(Qg + (size_t)(i0 + srw[it]) * DD + sce[it]);
        *(uint4*)&Qs[srw[it] * 72 + sce[it]] = v;
    }
    stage_kv(0, 0); CP_COMMIT;
    __syncthreads();

    uint32_t qa[4][4];
    #pragma unroll
    for (int ch = 0; ch < 4; ++ch)
        ldm_x4(qa[ch], &Qs[(qr + a_r) * 72 + ch * 16 + a_c]);
    // iter-0's block barrier protects Qs before iter-1 stages buffer 2.

    // ---- per-row ||q|| from fragments (rows live in 4-lane groups) ----
    float nq0 = 0.f, nq1 = 0.f;
    #pragma unroll
    for (int ch = 0; ch < 4; ++ch) {
        float2 f;
        f = __bfloat1622float2(*(__nv_bfloat162*)&qa[ch][0]);
        nq0 = fmaf(f.x, f.x, fmaf(f.y, f.y, nq0));
        f = __bfloat1622float2(*(__nv_bfloat162*)&qa[ch][2]);
        nq0 = fmaf(f.x, f.x, fmaf(f.y, f.y, nq0));
        f = __bfloat1622float2(*(__nv_bfloat162*)&qa[ch][1]);
        nq1 = fmaf(f.x, f.x, fmaf(f.y, f.y, nq1));
        f = __bfloat1622float2(*(__nv_bfloat162*)&qa[ch][3]);
        nq1 = fmaf(f.x, f.x, fmaf(f.y, f.y, nq1));
    }
    nq0 += __shfl_xor_sync(0xffffffffu, nq0, 1);
    nq0 += __shfl_xor_sync(0xffffffffu, nq0, 2);
    nq1 += __shfl_xor_sync(0xffffffffu, nq1, 1);
    nq1 += __shfl_xor_sync(0xffffffffu, nq1, 2);

    float maxk = sqrtf(__uint_as_float(g_maxk_bits[b * HH + h]));
    float maxc = dec_ord(g_maxc_bits[b]);
    float m0 = SCLOG * sqrtf(nq0) * maxk + maxc + 1.0f;
    float m1 = SCLOG * sqrtf(nq1) * maxk + maxc + 1.0f;

    int r0g = i0 + qr + g, r1g = r0g + 8;
    const float* adjr0 = adjb + (size_t)r0g * NN + 4 * t4;
    const float* adjr1 = adjb + (size_t)r1g * NN + 4 * t4;
    const float* cvq   = cv + 4 * t4;
    float rs0 = 0.f, rs1 = 0.f;
    float o[8][4] = {};

    for (int jt = 0; jt < NN / 64; ++jt) {
        int j0 = jt * 64;
        int buf = jt % 3;
        if (jt + 1 < NN / 64) { stage_kv(jt + 1, (jt + 1) % 3); CP_COMMIT; CP_WAIT1; }
        else                  { CP_WAIT0; }
        __syncthreads();

        const __nv_bfloat16* Kt = Kb0 + buf * TB;
        const __nv_bfloat16* Vt = Vb0 + buf * TB;

        // prefetch adjacency for chunk 0 (one float4 per row)
        float4 aq0 = *(const float4*)(adjr0 + j0);
        float4 aq1 = *(const float4*)(adjr1 + j0);

        // ---- fused per-16-key chunk: S -> p/pack -> PV ----
        #pragma unroll
        for (int ch = 0; ch < 4; ++ch) {
            float s2[2][4] = {};
            #pragma unroll
            for (int kch = 0; kch < 4; ++kch) {
                uint32_t kb[4];
                ldm_x4(kb, &Kt[(ch * 16 + k_r) * 72 + kch * 16 + k_c]);
                mma16(s2[0], qa[kch], kb[0], kb[1], s2[0]);
                mma16(s2[1], qa[kch], kb[2], kb[3], s2[1]);
            }

            // next chunk's adjacency while S settles
            float4 nq0v, nq1v;
            if (ch < 3) {
                nq0v = *(const float4*)(adjr0 + j0 + (ch + 1) * 16);
                nq1v = *(const float4*)(adjr1 + j0 + (ch + 1) * 16);
            }

            float4 cq = *(const float4*)(cvq + j0 + ch * 16);
            const float* cqa = (const float*)&cq;
            const float* a0a = (const float*)&aq0;
            const float* a1a = (const float*)&aq1;

            uint32_t pac[4];
            #pragma unroll
            for (int w = 0; w < 2; ++w) {
                float cA = cqa[2 * w], cB = cqa[2 * w + 1];
                float p00 = ex2f(fmaf(s2[w][0], SCLOG, cA - m0)) * (a0a[2 * w]     + 1e-9f);
                float p01 = ex2f(fmaf(s2[w][1], SCLOG, cB - m0)) * (a0a[2 * w + 1] + 1e-9f);
                float p10 = ex2f(fmaf(s2[w][2], SCLOG, cA - m1)) * (a1a[2 * w]     + 1e-9f);
                float p11 = ex2f(fmaf(s2[w][3], SCLOG, cB - m1)) * (a1a[2 * w + 1] + 1e-9f);
                rs0 += p00 + p01; rs1 += p10 + p11;
                pac[2 * w]     = pack_bf16(p00, p01);
                pac[2 * w + 1] = pack_bf16(p10, p11);
            }

            #pragma unroll
            for (int np = 0; np < 4; ++np) {
                uint32_t vb[4];
                ldm_x4_trans(vb, &Vt[(ch * 16 + v_r) * 72 + (2 * np + v_s) * 8]);
                mma16(o[2 * np],     pac, vb[0], vb[1], o[2 * np]);
                mma16(o[2 * np + 1], pac, vb[2], vb[3], o[2 * np + 1]);
            }

            if (ch < 3) { aq0 = nq0v; aq1 = nq1v; }
        }
    }

    // ---- single end-of-kernel l reduction ----
    rs0 += __shfl_xor_sync(0xffffffffu, rs0, 1);
    rs0 += __shfl_xor_sync(0xffffffffu, rs0, 2);
    rs1 += __shfl_xor_sync(0xffffffffu, rs1, 1);
    rs1 += __shfl_xor_sync(0xffffffffu, rs1, 2);

    // ---- epilogue: normalize + residual (fp32) ----
    float inv0 = __fdividef(1.0f, rs0);
    float inv1 = __fdividef(1.0f, rs1);
    #pragma unroll
    for (int n = 0; n < 8; ++n) {
        int col = h * HD + n * 8 + 2 * t4;
        float2 x0 = *(const float2*)(x + ((size_t)b * NN + r0g) * DD + col);
        float2 x1 = *(const float2*)(x + ((size_t)b * NN + r1g) * DD + col);
        float2 o0 = {fmaf(o[n][0], inv0, x0.x), fmaf(o[n][1], inv0, x0.y)};
        float2 o1 = {fmaf(o[n][2], inv1, x1.x), fmaf(o[n][3], inv1, x1.y)};
        *(float2*)(out + ((size_t)b * NN + r0g) * DD + col) = o0;
        *(float2*)(out + ((size_t)b * NN + r1g) * DD + col) = o1;
    }
}

// ---------------------------------------------------------------------------
extern "C" void kernel_launch(void* const* d_in, const int* in_sizes, int n_in,
                              void* d_out, int out_size)
{
    const float* x   = (const float*)d_in[0];
    const float* adj = (const float*)d_in[1];
    const float* Wq  = (const float*)d_in[2];
    const float* bq  = (const float*)d_in[3];
    const float* Wk  = (const float*)d_in[4];
    const float* bk  = (const float*)d_in[5];
    const float* Wv  = (const float*)d_in[6];
    const float* bv  = (const float*)d_in[7];
    const float* wg  = (const float*)d_in[8];
    // d_in[9] (b_g) cancels inside the softmax; unused.
    float* out = (float*)d_out;

    const int qkv_smem = (2 * 128 * 72 + 2 * 64 * 136) * 2;  // 71680 B
    cudaFuncSetAttribute((const void*)qkv_gemm,
                         cudaFuncAttributeMaxDynamicSharedMemorySize, qkv_smem);
    const int attn_smem = 6 * 64 * 72 * 2;                   // 55296 B
    cudaFuncSetAttribute((const void*)attn_kernel,
                         cudaFuncAttributeMaxDynamicSharedMemorySize, attn_smem);

    prep_kernel<<<896, 256>>>(x, wg, Wq, Wk, Wv);
    qkv_gemm<<<dim3(DD / 128, ROWS / 128, 3), 256, qkv_smem>>>(bq, bk, bv);
    attn_kernel<<<dim3(NN / 64, HH, BB), 128, attn_smem>>>(x, adj, out);
}